// round 1
// baseline (speedup 1.0000x reference)
#include <cuda_runtime.h>
#include <math.h>

#define Tn 1024
#define Bn 4
#define En 1024
#define Hn 16
#define DHn 64
#define RSPAN (2*Tn - 1)   // 2047

// ---------------- scratch (static device globals; no runtime alloc) ----------------
__device__ float g_q[(size_t)Bn*Hn*Tn*DHn];     // [B,H,T,DH]
__device__ float g_k[(size_t)Bn*Hn*Tn*DHn];
__device__ float g_v[(size_t)Bn*Hn*Tn*DHn];
__device__ float g_ctx[(size_t)Tn*Bn*En];       // [T,B,E]
__device__ float g_gate[Bn*Hn*Tn];              // gate_a_1 per (b,h,t)
__device__ float g_posb[Hn*RSPAN];              // rel_bias[bucket(rp)][h], rp = idx-(T-1)

// ---------------- pos-bias table ----------------
__global__ void posb_kernel(const float* __restrict__ rel_bias) {
    int idx = blockIdx.x * blockDim.x + threadIdx.x;
    if (idx >= RSPAN) return;
    int rp = idx - (Tn - 1);
    const int n = 16;          // NUM_BUCKETS/2
    const int max_exact = 8;   // n/2
    int bucket = (rp > 0) ? n : 0;
    int arp = abs(rp);
    int add;
    if (arp < max_exact) {
        add = arp;
    } else {
        // log(arp/8)/log(16)*8 == (log2(arp)-3)*2 ; exact at powers of two
        float v = (log2f((float)arp) - 3.0f) * 2.0f;
        add = max_exact + (int)v;
        if (add > n - 1) add = n - 1;
    }
    bucket += add;
    #pragma unroll
    for (int h = 0; h < Hn; h++)
        g_posb[h*RSPAN + idx] = rel_bias[bucket*Hn + h];
}

// ---------------- gate kernel: one warp per (b,h,t) ----------------
__global__ void gate_kernel(const float* __restrict__ query,
                            const float* __restrict__ grep_w,
                            const float* __restrict__ grep_b,
                            const float* __restrict__ grep_a) {
    int warp = blockIdx.x * (blockDim.x >> 5) + (threadIdx.x >> 5);
    int lane = threadIdx.x & 31;
    if (warp >= Bn*Hn*Tn) return;
    int t = warp % Tn;
    int h = (warp / Tn) % Hn;
    int b = warp / (Tn * Hn);
    const float* q = query + ((size_t)t*Bn + b)*En + h*DHn;
    float q0 = q[lane], q1 = q[lane + 32];
    float s0 = 0.f, s1 = 0.f;
    #pragma unroll
    for (int e = 0; e < 8; e++) {
        float p = q0 * grep_w[e*DHn + lane] + q1 * grep_w[e*DHn + lane + 32];
        #pragma unroll
        for (int o = 16; o; o >>= 1) p += __shfl_xor_sync(0xffffffffu, p, o);
        p += grep_b[e];
        if (e < 4) s0 += p; else s1 += p;
    }
    if (lane == 0) {
        float ga = 1.f / (1.f + __expf(-s0));
        float gb = 1.f / (1.f + __expf(-s1));
        g_gate[warp] = ga * (gb * grep_a[h] - 1.0f) + 2.0f;
    }
}

// ---------------- SGEMM: out = (A[M,K] @ W[N,K]^T + bias) * scale ----------------
// mode 0: out[r*N+c]   (row-major [M,N])
// mode 1: r=t*B+b, c=h*DH+d  ->  out[((b*H+h)*T+t)*DH + d]   (head-major QKV layout)
__global__ void __launch_bounds__(256)
gemm_bt(const float* __restrict__ A, const float* __restrict__ W,
        const float* __restrict__ bias, float* __restrict__ out,
        int M, int N, int K, float scale, int mode) {
    __shared__ float As[16*64];
    __shared__ float Bs[16*64];
    int tid = threadIdx.x;
    int tx = tid & 15, ty = tid >> 4;
    int m0 = blockIdx.y * 64, n0 = blockIdx.x * 64;
    int lr = tid >> 2;
    int lk = (tid & 3) << 2;
    const float* Ap = A + (size_t)(m0 + lr) * K + lk;
    const float* Wp = W + (size_t)(n0 + lr) * K + lk;
    float acc[4][4] = {};
    for (int kt = 0; kt < K; kt += 16) {
        float4 av = *(const float4*)(Ap + kt);
        float4 wv = *(const float4*)(Wp + kt);
        As[(lk+0)*64+lr]=av.x; As[(lk+1)*64+lr]=av.y; As[(lk+2)*64+lr]=av.z; As[(lk+3)*64+lr]=av.w;
        Bs[(lk+0)*64+lr]=wv.x; Bs[(lk+1)*64+lr]=wv.y; Bs[(lk+2)*64+lr]=wv.z; Bs[(lk+3)*64+lr]=wv.w;
        __syncthreads();
        #pragma unroll
        for (int k = 0; k < 16; k++) {
            float4 a  = *(const float4*)&As[k*64 + ty*4];
            float4 bv = *(const float4*)&Bs[k*64 + tx*4];
            acc[0][0] += a.x*bv.x; acc[0][1] += a.x*bv.y; acc[0][2] += a.x*bv.z; acc[0][3] += a.x*bv.w;
            acc[1][0] += a.y*bv.x; acc[1][1] += a.y*bv.y; acc[1][2] += a.y*bv.z; acc[1][3] += a.y*bv.w;
            acc[2][0] += a.z*bv.x; acc[2][1] += a.z*bv.y; acc[2][2] += a.z*bv.z; acc[2][3] += a.z*bv.w;
            acc[3][0] += a.w*bv.x; acc[3][1] += a.w*bv.y; acc[3][2] += a.w*bv.z; acc[3][3] += a.w*bv.w;
        }
        __syncthreads();
    }
    #pragma unroll
    for (int i = 0; i < 4; i++) {
        int r = m0 + ty*4 + i;
        #pragma unroll
        for (int j = 0; j < 4; j++) {
            int c = n0 + tx*4 + j;
            float v = (acc[i][j] + bias[c]) * scale;
            if (mode == 0) {
                out[(size_t)r*N + c] = v;
            } else {
                int t = r >> 2, b = r & 3;       // B = 4
                int h = c >> 6, d = c & 63;      // DH = 64
                out[((size_t)(b*Hn + h)*Tn + t)*DHn + d] = v;
            }
        }
    }
}

// ---------------- flash attention: 64x64 tiles, online softmax ----------------
// grid (16, H, B), block 256, dynamic smem 66304 B
__global__ void __launch_bounds__(256) attn_kernel() {
    extern __shared__ float sm[];
    float* Qst = sm;              // [d][r] 64x64
    float* Kst = sm + 4096;      // [d][s] 64x64
    float* Vs  = sm + 8192;      // [s][d] 64x64
    float* Pst = sm + 12288;     // [s][r] 64x64
    float* Ls  = sm + 16384;     // 127 diag bias values (+1 pad)
    float* gs  = sm + 16512;     // 64 gates

    int tid = threadIdx.x;
    int tx = tid & 15, ty = tid >> 4;
    int t0 = blockIdx.x * 64;
    int h  = blockIdx.y;
    int b  = blockIdx.z;

    size_t head_off = (size_t)(b*Hn + h) * Tn * DHn;
    const float* qbase = g_q + head_off;
    const float* kbase = g_k + head_off;
    const float* vbase = g_v + head_off;

    int lr = tid >> 2;
    int seg = (tid & 3) * 16;

    // load Q tile transposed: Qst[d][r]
    {
        const float* qp = qbase + (size_t)(t0 + lr)*DHn + seg;
        #pragma unroll
        for (int u = 0; u < 4; u++) {
            float4 v = *(const float4*)(qp + u*4);
            int d = seg + u*4;
            Qst[(d+0)*64+lr]=v.x; Qst[(d+1)*64+lr]=v.y; Qst[(d+2)*64+lr]=v.z; Qst[(d+3)*64+lr]=v.w;
        }
    }
    if (tid < 64) gs[tid] = g_gate[(b*Hn + h)*Tn + t0 + tid];

    float m[4], l[4], acc[4][4];
    #pragma unroll
    for (int i = 0; i < 4; i++) {
        m[i] = -1e30f; l[i] = 0.f;
        #pragma unroll
        for (int j = 0; j < 4; j++) acc[i][j] = 0.f;
    }

    for (int st = 0; st < 16; st++) {
        int s0 = st * 64;
        __syncthreads();  // protects Kst/Vs/Pst reuse; first iter: makes Qst/gs visible
        // load K transposed, V natural
        {
            const float* kp = kbase + (size_t)(s0 + lr)*DHn + seg;
            const float* vp = vbase + (size_t)(s0 + lr)*DHn + seg;
            #pragma unroll
            for (int u = 0; u < 4; u++) {
                float4 kv = *(const float4*)(kp + u*4);
                int d = seg + u*4;
                Kst[(d+0)*64+lr]=kv.x; Kst[(d+1)*64+lr]=kv.y; Kst[(d+2)*64+lr]=kv.z; Kst[(d+3)*64+lr]=kv.w;
                float4 vv = *(const float4*)(vp + u*4);
                *(float4*)&Vs[lr*64 + d] = vv;
            }
        }
        if (tid < 127)  // rp = s - t = (s0-t0) + (c-r); Ls[c-r+63]
            Ls[tid] = g_posb[h*RSPAN + (s0 - t0) + 960 + tid];
        __syncthreads();

        // S = Q K^T (+bias)
        float S[4][4] = {};
        #pragma unroll 8
        for (int d = 0; d < 64; d++) {
            float4 a  = *(const float4*)&Qst[d*64 + ty*4];
            float4 kk = *(const float4*)&Kst[d*64 + tx*4];
            S[0][0] += a.x*kk.x; S[0][1] += a.x*kk.y; S[0][2] += a.x*kk.z; S[0][3] += a.x*kk.w;
            S[1][0] += a.y*kk.x; S[1][1] += a.y*kk.y; S[1][2] += a.y*kk.z; S[1][3] += a.y*kk.w;
            S[2][0] += a.z*kk.x; S[2][1] += a.z*kk.y; S[2][2] += a.z*kk.z; S[2][3] += a.z*kk.w;
            S[3][0] += a.w*kk.x; S[3][1] += a.w*kk.y; S[3][2] += a.w*kk.z; S[3][3] += a.w*kk.w;
        }
        #pragma unroll
        for (int i = 0; i < 4; i++) {
            int r = ty*4 + i;
            float gr = gs[r];
            #pragma unroll
            for (int j = 0; j < 4; j++) {
                int c = tx*4 + j;
                S[i][j] += gr * Ls[c - r + 63];
            }
        }
        // online softmax per row (reduce across tx: 16-lane groups via xor<16)
        #pragma unroll
        for (int i = 0; i < 4; i++) {
            float tm = fmaxf(fmaxf(S[i][0], S[i][1]), fmaxf(S[i][2], S[i][3]));
            #pragma unroll
            for (int o = 8; o; o >>= 1) tm = fmaxf(tm, __shfl_xor_sync(0xffffffffu, tm, o));
            float mn = fmaxf(m[i], tm);
            float corr = __expf(m[i] - mn);
            m[i] = mn;
            float rs = 0.f;
            #pragma unroll
            for (int j = 0; j < 4; j++) {
                S[i][j] = __expf(S[i][j] - mn);
                rs += S[i][j];
            }
            #pragma unroll
            for (int o = 8; o; o >>= 1) rs += __shfl_xor_sync(0xffffffffu, rs, o);
            l[i] = l[i]*corr + rs;
            #pragma unroll
            for (int j = 0; j < 4; j++) {
                acc[i][j] *= corr;
                Pst[(tx*4 + j)*64 + ty*4 + i] = S[i][j];
            }
        }
        __syncthreads();
        // acc += P V
        #pragma unroll 8
        for (int s = 0; s < 64; s++) {
            float4 p = *(const float4*)&Pst[s*64 + ty*4];
            float4 v = *(const float4*)&Vs[s*64 + tx*4];
            acc[0][0] += p.x*v.x; acc[0][1] += p.x*v.y; acc[0][2] += p.x*v.z; acc[0][3] += p.x*v.w;
            acc[1][0] += p.y*v.x; acc[1][1] += p.y*v.y; acc[1][2] += p.y*v.z; acc[1][3] += p.y*v.w;
            acc[2][0] += p.z*v.x; acc[2][1] += p.z*v.y; acc[2][2] += p.z*v.z; acc[2][3] += p.z*v.w;
            acc[3][0] += p.w*v.x; acc[3][1] += p.w*v.y; acc[3][2] += p.w*v.z; acc[3][3] += p.w*v.w;
        }
    }

    // write ctx[t, b, h*64+d]
    #pragma unroll
    for (int i = 0; i < 4; i++) {
        int t = t0 + ty*4 + i;
        float inv = 1.f / l[i];
        #pragma unroll
        for (int j = 0; j < 4; j++) {
            int d = tx*4 + j;
            g_ctx[((size_t)t*Bn + b)*En + h*DHn + d] = acc[i][j] * inv;
        }
    }
}

// ---------------- launch ----------------
extern "C" void kernel_launch(void* const* d_in, const int* in_sizes, int n_in,
                              void* d_out, int out_size) {
    const float* query  = (const float*)d_in[0];
    const float* q_w    = (const float*)d_in[1];
    const float* q_b    = (const float*)d_in[2];
    const float* k_w    = (const float*)d_in[3];
    const float* k_b    = (const float*)d_in[4];
    const float* v_w    = (const float*)d_in[5];
    const float* v_b    = (const float*)d_in[6];
    const float* out_w  = (const float*)d_in[7];
    const float* out_b  = (const float*)d_in[8];
    const float* rel_bias = (const float*)d_in[9];
    const float* grep_w = (const float*)d_in[10];
    const float* grep_b = (const float*)d_in[11];
    const float* grep_a = (const float*)d_in[12];
    float* out = (float*)d_out;

    float* p_q;  cudaGetSymbolAddress((void**)&p_q,  g_q);
    float* p_k;  cudaGetSymbolAddress((void**)&p_k,  g_k);
    float* p_v;  cudaGetSymbolAddress((void**)&p_v,  g_v);
    float* p_ctx; cudaGetSymbolAddress((void**)&p_ctx, g_ctx);

    const int ATTN_SMEM = 66304;
    cudaFuncSetAttribute(attn_kernel, cudaFuncAttributeMaxDynamicSharedMemorySize, ATTN_SMEM);

    posb_kernel<<<(RSPAN + 255)/256, 256>>>(rel_bias);
    gate_kernel<<<(Bn*Hn*Tn)/4, 128>>>(query, grep_w, grep_b, grep_a);

    const int M = Tn*Bn, N = En, K = En;
    dim3 gg(N/64, M/64);
    const float scaling = 0.125f;  // DH^-0.5
    gemm_bt<<<gg, 256>>>(query, q_w, q_b, p_q, M, N, K, scaling, 1);
    gemm_bt<<<gg, 256>>>(query, k_w, k_b, p_k, M, N, K, 1.0f, 1);
    gemm_bt<<<gg, 256>>>(query, v_w, v_b, p_v, M, N, K, 1.0f, 1);

    dim3 ga(Tn/64, Hn, Bn);
    attn_kernel<<<ga, 256, ATTN_SMEM>>>();

    gemm_bt<<<gg, 256>>>(p_ctx, out_w, out_b, out, M, N, K, 1.0f, 0);

    (void)in_sizes; (void)n_in; (void)out_size;
}

// round 3
// speedup vs baseline: 1.6583x; 1.6583x over previous
#include <cuda_runtime.h>
#include <cuda_bf16.h>
#include <math.h>
#include <cstdint>

#define Tn 1024
#define Bn 4
#define En 1024
#define Hn 16
#define DHn 64
#define RSPAN (2*Tn - 1)   // 2047

// ---------------- scratch (static device globals; no runtime alloc) ----------------
__device__ float g_q[(size_t)Bn*Hn*Tn*DHn];     // [B,H,T,DH]
__device__ float g_k[(size_t)Bn*Hn*Tn*DHn];
__device__ float g_v[(size_t)Bn*Hn*Tn*DHn];
__device__ float g_ctx[(size_t)Tn*Bn*En];       // [T,B,E]
__device__ float g_gate[Bn*Hn*Tn];
__device__ float g_posb[Hn*RSPAN];

// bf16 hi/lo splits
__device__ __nv_bfloat16 g_xhi[(size_t)Tn*Bn*En];   // activations (query, later ctx)
__device__ __nv_bfloat16 g_xlo[(size_t)Tn*Bn*En];
__device__ __nv_bfloat16 g_whi[4][(size_t)En*En];   // q_w,k_w,v_w,out_w
__device__ __nv_bfloat16 g_wlo[4][(size_t)En*En];

// ================= helpers =================
__device__ __forceinline__ uint32_t smem_u32(const void* p) {
    uint32_t a;
    asm("{ .reg .u64 t; cvta.to.shared.u64 t, %1; cvt.u32.u64 %0, t; }" : "=r"(a) : "l"(p));
    return a;
}
__device__ __forceinline__ void cpa16(uint32_t dst, const void* src) {
    asm volatile("cp.async.cg.shared.global [%0], [%1], 16;" :: "r"(dst), "l"(src));
}
#define CP_COMMIT() asm volatile("cp.async.commit_group;" ::: "memory")
#define CP_WAIT(n)  asm volatile("cp.async.wait_group %0;" :: "n"(n) : "memory")

#define LDSM_X4(r, a) \
    asm volatile("ldmatrix.sync.aligned.m8n8.x4.shared.b16 {%0,%1,%2,%3}, [%4];" \
        : "=r"((r)[0]), "=r"((r)[1]), "=r"((r)[2]), "=r"((r)[3]) : "r"(a))

#define MMA16816(c, a, b0, b1) \
    asm volatile("mma.sync.aligned.m16n8k16.row.col.f32.bf16.bf16.f32 " \
        "{%0,%1,%2,%3}, {%4,%5,%6,%7}, {%8,%9}, {%0,%1,%2,%3};" \
        : "+f"((c)[0]), "+f"((c)[1]), "+f"((c)[2]), "+f"((c)[3]) \
        : "r"((a)[0]), "r"((a)[1]), "r"((a)[2]), "r"((a)[3]), "r"(b0), "r"(b1))

// ================= HMMA bf16-split GEMM =================
// out[M=4096, N=1024] = (Ahi+Alo)[M,K=1024] @ (Whi+Wlo)[N,K]^T (3-term split) + bias, *scale
#define ST 40                   // smem row stride in halves (conflict-free ldmatrix)
#define TILE_H (128*ST)         // halves per 128x32 tile
#define BUF_H  (4*TILE_H)       // Ahi,Alo,Whi,Wlo
#define SMEM_G (2*BUF_H*2)      // bytes: 81920
#define NCH 32                  // K/32

__device__ __forceinline__ void load_tile_mma(uint32_t sdst, const __nv_bfloat16* g,
                                              int r0, int kc, int tid) {
    #pragma unroll
    for (int it = 0; it < 2; it++) {
        int idx = tid + it * 256;
        int row = idx >> 2, seg = idx & 3;
        uint32_t dst = sdst + (uint32_t)(row * ST) * 2u + seg * 16;
        const char* src = (const char*)(g + (size_t)(r0 + row) * 1024 + kc * 32 + seg * 8);
        cpa16(dst, src);
    }
}

__global__ void __launch_bounds__(256, 1)
gemm_mma(const __nv_bfloat16* __restrict__ Ahi, const __nv_bfloat16* __restrict__ Alo,
         const __nv_bfloat16* __restrict__ Whi, const __nv_bfloat16* __restrict__ Wlo,
         const float* __restrict__ bias, float* __restrict__ out, float scale, int mode) {
    extern __shared__ char smraw[];
    uint32_t sb = smem_u32(smraw);
    int tid = threadIdx.x, wid = tid >> 5, lane = tid & 31;
    int m0 = blockIdx.y * 128, n0 = blockIdx.x * 128;
    int warp_m = wid & 1;        // 0..1 -> 64-row slab
    int warp_n = wid >> 1;       // 0..3 -> 32-col slab

    // per-lane ldmatrix byte offsets (within a tile)
    // A: row = (lane&15), k-half-offset = (lane>>4)*8
    uint32_t a_off[4];
    #pragma unroll
    for (int mi = 0; mi < 4; mi++) {
        int arow = warp_m * 64 + mi * 16 + (lane & 15);
        a_off[mi] = (uint32_t)(arow * ST + (lane >> 4) * 8) * 2u;
    }
    // B (x4 covers two 8-col n-tiles): n = base + ((lane>>4)&1)*8 + (lane&7), k-off = ((lane>>3)&1)*8
    uint32_t b_off[2];
    #pragma unroll
    for (int nip = 0; nip < 2; nip++) {
        int nrow = warp_n * 32 + nip * 16 + ((lane >> 4) & 1) * 8 + (lane & 7);
        b_off[nip] = (uint32_t)(nrow * ST + ((lane >> 3) & 1) * 8) * 2u;
    }

    float acc[4][4][4];
    #pragma unroll
    for (int i = 0; i < 4; i++)
        #pragma unroll
        for (int j = 0; j < 4; j++)
            #pragma unroll
            for (int q = 0; q < 4; q++) acc[i][j][q] = 0.f;

    // prologue
    #pragma unroll
    for (int pc = 0; pc < 2; pc++) {
        uint32_t bb = sb + pc * (BUF_H * 2);
        load_tile_mma(bb + 0 * TILE_H * 2, Ahi, m0, pc, tid);
        load_tile_mma(bb + 1 * TILE_H * 2, Alo, m0, pc, tid);
        load_tile_mma(bb + 2 * TILE_H * 2, Whi, n0, pc, tid);
        load_tile_mma(bb + 3 * TILE_H * 2, Wlo, n0, pc, tid);
        CP_COMMIT();
    }

    #pragma unroll 1
    for (int kc = 0; kc < NCH; kc++) {
        uint32_t bb = sb + (kc & 1) * (BUF_H * 2);
        if (kc < NCH - 1) CP_WAIT(1); else CP_WAIT(0);
        __syncthreads();

        uint32_t Ah = bb, Al = bb + TILE_H * 2, Wh = bb + 2 * TILE_H * 2, Wl = bb + 3 * TILE_H * 2;
        #pragma unroll
        for (int ks = 0; ks < 2; ks++) {
            uint32_t koff = ks * 32;   // 16 halves
            uint32_t ah[4][4], al[4][4], bh[2][4], bl[2][4];
            #pragma unroll
            for (int mi = 0; mi < 4; mi++) {
                LDSM_X4(ah[mi], Ah + a_off[mi] + koff);
                LDSM_X4(al[mi], Al + a_off[mi] + koff);
            }
            #pragma unroll
            for (int nip = 0; nip < 2; nip++) {
                LDSM_X4(bh[nip], Wh + b_off[nip] + koff);
                LDSM_X4(bl[nip], Wl + b_off[nip] + koff);
            }
            #pragma unroll
            for (int mi = 0; mi < 4; mi++) {
                #pragma unroll
                for (int ni = 0; ni < 4; ni++) {
                    int nip = ni >> 1, hf = (ni & 1) * 2;
                    MMA16816(acc[mi][ni], ah[mi], bh[nip][hf], bh[nip][hf + 1]);
                    MMA16816(acc[mi][ni], ah[mi], bl[nip][hf], bl[nip][hf + 1]);
                    MMA16816(acc[mi][ni], al[mi], bh[nip][hf], bh[nip][hf + 1]);
                }
            }
        }
        __syncthreads();
        if (kc + 2 < NCH) {
            load_tile_mma(bb + 0 * TILE_H * 2, Ahi, m0, kc + 2, tid);
            load_tile_mma(bb + 1 * TILE_H * 2, Alo, m0, kc + 2, tid);
            load_tile_mma(bb + 2 * TILE_H * 2, Whi, n0, kc + 2, tid);
            load_tile_mma(bb + 3 * TILE_H * 2, Wlo, n0, kc + 2, tid);
            CP_COMMIT();
        }
    }

    // epilogue: c0,c1 -> (row, col..col+1), c2,c3 -> (row+8, ...)
    int rbase = m0 + warp_m * 64 + (lane >> 2);
    int cbase = n0 + warp_n * 32 + (lane & 3) * 2;
    #pragma unroll
    for (int mi = 0; mi < 4; mi++) {
        #pragma unroll
        for (int ni = 0; ni < 4; ni++) {
            int c = cbase + ni * 8;
            float b0 = bias[c], b1 = bias[c + 1];
            #pragma unroll
            for (int half = 0; half < 2; half++) {
                int r = rbase + mi * 16 + half * 8;
                float2 v;
                v.x = (acc[mi][ni][half * 2 + 0] + b0) * scale;
                v.y = (acc[mi][ni][half * 2 + 1] + b1) * scale;
                if (mode == 0) {
                    *(float2*)(out + (size_t)r * 1024 + c) = v;
                } else {
                    int t = r >> 2, b = r & 3;
                    int h = c >> 6, d = c & 63;
                    *(float2*)(out + ((size_t)(b * Hn + h) * Tn + t) * DHn + d) = v;
                }
            }
        }
    }
}

// ================= split fp32 -> bf16 hi/lo =================
__global__ void split_kernel(const float* __restrict__ src,
                             __nv_bfloat16* __restrict__ hi,
                             __nv_bfloat16* __restrict__ lo, int n) {
    int i = (blockIdx.x * blockDim.x + threadIdx.x) * 4;
    if (i >= n) return;
    float4 v = *(const float4*)(src + i);
    __nv_bfloat16 h0 = __float2bfloat16(v.x), h1 = __float2bfloat16(v.y);
    __nv_bfloat16 h2 = __float2bfloat16(v.z), h3 = __float2bfloat16(v.w);
    __nv_bfloat16 l0 = __float2bfloat16(v.x - __bfloat162float(h0));
    __nv_bfloat16 l1 = __float2bfloat16(v.y - __bfloat162float(h1));
    __nv_bfloat16 l2 = __float2bfloat16(v.z - __bfloat162float(h2));
    __nv_bfloat16 l3 = __float2bfloat16(v.w - __bfloat162float(h3));
    __nv_bfloat162* hp = (__nv_bfloat162*)(hi + i);
    __nv_bfloat162* lp = (__nv_bfloat162*)(lo + i);
    hp[0] = __nv_bfloat162(h0, h1); hp[1] = __nv_bfloat162(h2, h3);
    lp[0] = __nv_bfloat162(l0, l1); lp[1] = __nv_bfloat162(l2, l3);
}

// ---------------- pos-bias table ----------------
__global__ void posb_kernel(const float* __restrict__ rel_bias) {
    int idx = blockIdx.x * blockDim.x + threadIdx.x;
    if (idx >= RSPAN) return;
    int rp = idx - (Tn - 1);
    const int n = 16;
    const int max_exact = 8;
    int bucket = (rp > 0) ? n : 0;
    int arp = abs(rp);
    int add;
    if (arp < max_exact) {
        add = arp;
    } else {
        float v = (log2f((float)arp) - 3.0f) * 2.0f;
        add = max_exact + (int)v;
        if (add > n - 1) add = n - 1;
    }
    bucket += add;
    #pragma unroll
    for (int h = 0; h < Hn; h++)
        g_posb[h*RSPAN + idx] = rel_bias[bucket*Hn + h];
}

// ---------------- gate kernel ----------------
__global__ void gate_kernel(const float* __restrict__ query,
                            const float* __restrict__ grep_w,
                            const float* __restrict__ grep_b,
                            const float* __restrict__ grep_a) {
    int warp = blockIdx.x * (blockDim.x >> 5) + (threadIdx.x >> 5);
    int lane = threadIdx.x & 31;
    if (warp >= Bn*Hn*Tn) return;
    int t = warp % Tn;
    int h = (warp / Tn) % Hn;
    int b = warp / (Tn * Hn);
    const float* q = query + ((size_t)t*Bn + b)*En + h*DHn;
    float q0 = q[lane], q1 = q[lane + 32];
    float s0 = 0.f, s1 = 0.f;
    #pragma unroll
    for (int e = 0; e < 8; e++) {
        float p = q0 * grep_w[e*DHn + lane] + q1 * grep_w[e*DHn + lane + 32];
        #pragma unroll
        for (int o = 16; o; o >>= 1) p += __shfl_xor_sync(0xffffffffu, p, o);
        p += grep_b[e];
        if (e < 4) s0 += p; else s1 += p;
    }
    if (lane == 0) {
        float ga = 1.f / (1.f + __expf(-s0));
        float gb = 1.f / (1.f + __expf(-s1));
        g_gate[warp] = ga * (gb * grep_a[h] - 1.0f) + 2.0f;
    }
}

// ---------------- flash attention (fp32) ----------------
__global__ void __launch_bounds__(256) attn_kernel() {
    extern __shared__ float sm[];
    float* Qst = sm;
    float* Kst = sm + 4096;
    float* Vs  = sm + 8192;
    float* Pst = sm + 12288;
    float* Ls  = sm + 16384;
    float* gs  = sm + 16512;

    int tid = threadIdx.x;
    int tx = tid & 15, ty = tid >> 4;
    int t0 = blockIdx.x * 64;
    int h  = blockIdx.y;
    int b  = blockIdx.z;

    size_t head_off = (size_t)(b*Hn + h) * Tn * DHn;
    const float* qbase = g_q + head_off;
    const float* kbase = g_k + head_off;
    const float* vbase = g_v + head_off;

    int lr = tid >> 2;
    int seg = (tid & 3) * 16;

    {
        const float* qp = qbase + (size_t)(t0 + lr)*DHn + seg;
        #pragma unroll
        for (int u = 0; u < 4; u++) {
            float4 v = *(const float4*)(qp + u*4);
            int d = seg + u*4;
            Qst[(d+0)*64+lr]=v.x; Qst[(d+1)*64+lr]=v.y; Qst[(d+2)*64+lr]=v.z; Qst[(d+3)*64+lr]=v.w;
        }
    }
    if (tid < 64) gs[tid] = g_gate[(b*Hn + h)*Tn + t0 + tid];

    float m[4], l[4], acc[4][4];
    #pragma unroll
    for (int i = 0; i < 4; i++) {
        m[i] = -1e30f; l[i] = 0.f;
        #pragma unroll
        for (int j = 0; j < 4; j++) acc[i][j] = 0.f;
    }

    for (int st = 0; st < 16; st++) {
        int s0 = st * 64;
        __syncthreads();
        {
            const float* kp = kbase + (size_t)(s0 + lr)*DHn + seg;
            const float* vp = vbase + (size_t)(s0 + lr)*DHn + seg;
            #pragma unroll
            for (int u = 0; u < 4; u++) {
                float4 kv = *(const float4*)(kp + u*4);
                int d = seg + u*4;
                Kst[(d+0)*64+lr]=kv.x; Kst[(d+1)*64+lr]=kv.y; Kst[(d+2)*64+lr]=kv.z; Kst[(d+3)*64+lr]=kv.w;
                float4 vv = *(const float4*)(vp + u*4);
                *(float4*)&Vs[lr*64 + d] = vv;
            }
        }
        if (tid < 127)
            Ls[tid] = g_posb[h*RSPAN + (s0 - t0) + 960 + tid];
        __syncthreads();

        float S[4][4] = {};
        #pragma unroll 8
        for (int d = 0; d < 64; d++) {
            float4 a  = *(const float4*)&Qst[d*64 + ty*4];
            float4 kk = *(const float4*)&Kst[d*64 + tx*4];
            S[0][0] += a.x*kk.x; S[0][1] += a.x*kk.y; S[0][2] += a.x*kk.z; S[0][3] += a.x*kk.w;
            S[1][0] += a.y*kk.x; S[1][1] += a.y*kk.y; S[1][2] += a.y*kk.z; S[1][3] += a.y*kk.w;
            S[2][0] += a.z*kk.x; S[2][1] += a.z*kk.y; S[2][2] += a.z*kk.z; S[2][3] += a.z*kk.w;
            S[3][0] += a.w*kk.x; S[3][1] += a.w*kk.y; S[3][2] += a.w*kk.z; S[3][3] += a.w*kk.w;
        }
        #pragma unroll
        for (int i = 0; i < 4; i++) {
            int r = ty*4 + i;
            float gr = gs[r];
            #pragma unroll
            for (int j = 0; j < 4; j++) {
                int c = tx*4 + j;
                S[i][j] += gr * Ls[c - r + 63];
            }
        }
        #pragma unroll
        for (int i = 0; i < 4; i++) {
            float tm = fmaxf(fmaxf(S[i][0], S[i][1]), fmaxf(S[i][2], S[i][3]));
            #pragma unroll
            for (int o = 8; o; o >>= 1) tm = fmaxf(tm, __shfl_xor_sync(0xffffffffu, tm, o));
            float mn = fmaxf(m[i], tm);
            float corr = __expf(m[i] - mn);
            m[i] = mn;
            float rs = 0.f;
            #pragma unroll
            for (int j = 0; j < 4; j++) {
                S[i][j] = __expf(S[i][j] - mn);
                rs += S[i][j];
            }
            #pragma unroll
            for (int o = 8; o; o >>= 1) rs += __shfl_xor_sync(0xffffffffu, rs, o);
            l[i] = l[i]*corr + rs;
            #pragma unroll
            for (int j = 0; j < 4; j++) {
                acc[i][j] *= corr;
                Pst[(tx*4 + j)*64 + ty*4 + i] = S[i][j];
            }
        }
        __syncthreads();
        #pragma unroll 8
        for (int s = 0; s < 64; s++) {
            float4 p = *(const float4*)&Pst[s*64 + ty*4];
            float4 v = *(const float4*)&Vs[s*64 + tx*4];
            acc[0][0] += p.x*v.x; acc[0][1] += p.x*v.y; acc[0][2] += p.x*v.z; acc[0][3] += p.x*v.w;
            acc[1][0] += p.y*v.x; acc[1][1] += p.y*v.y; acc[1][2] += p.y*v.z; acc[1][3] += p.y*v.w;
            acc[2][0] += p.z*v.x; acc[2][1] += p.z*v.y; acc[2][2] += p.z*v.z; acc[2][3] += p.z*v.w;
            acc[3][0] += p.w*v.x; acc[3][1] += p.w*v.y; acc[3][2] += p.w*v.z; acc[3][3] += p.w*v.w;
        }
    }

    #pragma unroll
    for (int i = 0; i < 4; i++) {
        int t = t0 + ty*4 + i;
        float inv = 1.f / l[i];
        #pragma unroll
        for (int j = 0; j < 4; j++) {
            int d = tx*4 + j;
            g_ctx[((size_t)t*Bn + b)*En + h*DHn + d] = acc[i][j] * inv;
        }
    }
}

// ---------------- launch ----------------
extern "C" void kernel_launch(void* const* d_in, const int* in_sizes, int n_in,
                              void* d_out, int out_size) {
    const float* query  = (const float*)d_in[0];
    const float* q_w    = (const float*)d_in[1];
    const float* q_b    = (const float*)d_in[2];
    const float* k_w    = (const float*)d_in[3];
    const float* k_b    = (const float*)d_in[4];
    const float* v_w    = (const float*)d_in[5];
    const float* v_b    = (const float*)d_in[6];
    const float* out_w  = (const float*)d_in[7];
    const float* out_b  = (const float*)d_in[8];
    const float* rel_bias = (const float*)d_in[9];
    const float* grep_w = (const float*)d_in[10];
    const float* grep_b = (const float*)d_in[11];
    const float* grep_a = (const float*)d_in[12];
    float* out = (float*)d_out;

    float* p_q;   cudaGetSymbolAddress((void**)&p_q,   g_q);
    float* p_k;   cudaGetSymbolAddress((void**)&p_k,   g_k);
    float* p_v;   cudaGetSymbolAddress((void**)&p_v,   g_v);
    float* p_ctx; cudaGetSymbolAddress((void**)&p_ctx, g_ctx);
    __nv_bfloat16* p_xhi; cudaGetSymbolAddress((void**)&p_xhi, g_xhi);
    __nv_bfloat16* p_xlo; cudaGetSymbolAddress((void**)&p_xlo, g_xlo);
    __nv_bfloat16* p_whi; cudaGetSymbolAddress((void**)&p_whi, g_whi);
    __nv_bfloat16* p_wlo; cudaGetSymbolAddress((void**)&p_wlo, g_wlo);

    const int ATTN_SMEM = 66304;
    cudaFuncSetAttribute(attn_kernel, cudaFuncAttributeMaxDynamicSharedMemorySize, ATTN_SMEM);
    cudaFuncSetAttribute(gemm_mma, cudaFuncAttributeMaxDynamicSharedMemorySize, SMEM_G);

    posb_kernel<<<(RSPAN + 255)/256, 256>>>(rel_bias);
    gate_kernel<<<(Bn*Hn*Tn)/4, 128>>>(query, grep_w, grep_b, grep_a);

    const int NA = Tn*Bn*En;   // 4M activations
    const int NW = En*En;      // 1M per weight
    split_kernel<<<NA/1024, 256>>>(query, p_xhi, p_xlo, NA);
    split_kernel<<<NW/1024, 256>>>(q_w,   p_whi + 0*(size_t)NW, p_wlo + 0*(size_t)NW, NW);
    split_kernel<<<NW/1024, 256>>>(k_w,   p_whi + 1*(size_t)NW, p_wlo + 1*(size_t)NW, NW);
    split_kernel<<<NW/1024, 256>>>(v_w,   p_whi + 2*(size_t)NW, p_wlo + 2*(size_t)NW, NW);
    split_kernel<<<NW/1024, 256>>>(out_w, p_whi + 3*(size_t)NW, p_wlo + 3*(size_t)NW, NW);

    dim3 gg(En/128, (Tn*Bn)/128);   // (8, 32)
    const float scaling = 0.125f;   // DH^-0.5
    gemm_mma<<<gg, 256, SMEM_G>>>(p_xhi, p_xlo, p_whi + 0*(size_t)NW, p_wlo + 0*(size_t)NW, q_b, p_q, scaling, 1);
    gemm_mma<<<gg, 256, SMEM_G>>>(p_xhi, p_xlo, p_whi + 1*(size_t)NW, p_wlo + 1*(size_t)NW, k_b, p_k, 1.0f, 1);
    gemm_mma<<<gg, 256, SMEM_G>>>(p_xhi, p_xlo, p_whi + 2*(size_t)NW, p_wlo + 2*(size_t)NW, v_b, p_v, 1.0f, 1);

    dim3 ga(Tn/64, Hn, Bn);
    attn_kernel<<<ga, 256, ATTN_SMEM>>>();

    split_kernel<<<NA/1024, 256>>>(p_ctx, p_xhi, p_xlo, NA);
    gemm_mma<<<gg, 256, SMEM_G>>>(p_xhi, p_xlo, p_whi + 3*(size_t)NW, p_wlo + 3*(size_t)NW, out_b, out, 1.0f, 0);

    (void)in_sizes; (void)n_in; (void)out_size;
}

// round 4
// speedup vs baseline: 2.8991x; 1.7483x over previous
#include <cuda_runtime.h>
#include <cuda_bf16.h>
#include <math.h>
#include <cstdint>

#define Tn 1024
#define Bn 4
#define En 1024
#define Hn 16
#define DHn 64
#define RSPAN (2*Tn - 1)   // 2047

// ---------------- scratch ----------------
__device__ float g_gate[Bn*Hn*Tn];
__device__ float g_posb[Hn*RSPAN];

__device__ __nv_bfloat16 g_xhi[(size_t)Tn*Bn*En];   // activations (query split / ctx)
__device__ __nv_bfloat16 g_xlo[(size_t)Tn*Bn*En];
__device__ __nv_bfloat16 g_whi[4][(size_t)En*En];   // q_w,k_w,v_w,out_w
__device__ __nv_bfloat16 g_wlo[4][(size_t)En*En];

__device__ __nv_bfloat16 g_qhi[(size_t)Bn*Hn*Tn*DHn];  // [B,H,T,DH]
__device__ __nv_bfloat16 g_qlo[(size_t)Bn*Hn*Tn*DHn];
__device__ __nv_bfloat16 g_khi[(size_t)Bn*Hn*Tn*DHn];
__device__ __nv_bfloat16 g_klo[(size_t)Bn*Hn*Tn*DHn];
__device__ __nv_bfloat16 g_vhi[(size_t)Bn*Hn*Tn*DHn];
__device__ __nv_bfloat16 g_vlo[(size_t)Bn*Hn*Tn*DHn];

// ================= helpers =================
__device__ __forceinline__ uint32_t smem_u32(const void* p) {
    uint32_t a;
    asm("{ .reg .u64 t; cvta.to.shared.u64 t, %1; cvt.u32.u64 %0, t; }" : "=r"(a) : "l"(p));
    return a;
}
__device__ __forceinline__ void cpa16(uint32_t dst, const void* src) {
    asm volatile("cp.async.cg.shared.global [%0], [%1], 16;" :: "r"(dst), "l"(src));
}
#define CP_COMMIT() asm volatile("cp.async.commit_group;" ::: "memory")
#define CP_WAIT(n)  asm volatile("cp.async.wait_group %0;" :: "n"(n) : "memory")

#define LDSM_X4(r, a) \
    asm volatile("ldmatrix.sync.aligned.m8n8.x4.shared.b16 {%0,%1,%2,%3}, [%4];" \
        : "=r"((r)[0]), "=r"((r)[1]), "=r"((r)[2]), "=r"((r)[3]) : "r"(a))
#define LDSM_X4_T(r, a) \
    asm volatile("ldmatrix.sync.aligned.m8n8.x4.trans.shared.b16 {%0,%1,%2,%3}, [%4];" \
        : "=r"((r)[0]), "=r"((r)[1]), "=r"((r)[2]), "=r"((r)[3]) : "r"(a))

#define MMA16816(c, a, b0, b1) \
    asm volatile("mma.sync.aligned.m16n8k16.row.col.f32.bf16.bf16.f32 " \
        "{%0,%1,%2,%3}, {%4,%5,%6,%7}, {%8,%9}, {%0,%1,%2,%3};" \
        : "+f"((c)[0]), "+f"((c)[1]), "+f"((c)[2]), "+f"((c)[3]) \
        : "r"((a)[0]), "r"((a)[1]), "r"((a)[2]), "r"((a)[3]), "r"(b0), "r"(b1))

__device__ __forceinline__ uint32_t pack_bf16x2(float lo, float hi) {
    uint32_t r;
    asm("cvt.rn.bf16x2.f32 %0, %1, %2;" : "=r"(r) : "f"(hi), "f"(lo));
    return r;
}
__device__ __forceinline__ float bf16_rt(float x) {
    return __bfloat162float(__float2bfloat16(x));
}

// ================= HMMA bf16-split GEMM =================
#define ST 40
#define TILE_H (128*ST)
#define BUF_H  (4*TILE_H)
#define SMEM_G (2*BUF_H*2)
#define NCH 32

__device__ __forceinline__ void load_tile_mma(uint32_t sdst, const __nv_bfloat16* g,
                                              int r0, int kc, int tid) {
    #pragma unroll
    for (int it = 0; it < 2; it++) {
        int idx = tid + it * 256;
        int row = idx >> 2, seg = idx & 3;
        uint32_t dst = sdst + (uint32_t)(row * ST) * 2u + seg * 16;
        const char* src = (const char*)(g + (size_t)(r0 + row) * 1024 + kc * 32 + seg * 8);
        cpa16(dst, src);
    }
}

__global__ void __launch_bounds__(256, 1)
gemm_mma(const __nv_bfloat16* __restrict__ Ahi, const __nv_bfloat16* __restrict__ Alo,
         const __nv_bfloat16* __restrict__ Whi, const __nv_bfloat16* __restrict__ Wlo,
         const float* __restrict__ bias, float* __restrict__ outf,
         __nv_bfloat16* __restrict__ ohi, __nv_bfloat16* __restrict__ olo,
         float scale, int mode) {
    extern __shared__ char smraw[];
    uint32_t sb = smem_u32(smraw);
    int tid = threadIdx.x, wid = tid >> 5, lane = tid & 31;
    int m0 = blockIdx.y * 128, n0 = blockIdx.x * 128;
    int warp_m = wid & 1;
    int warp_n = wid >> 1;

    uint32_t a_off[4];
    #pragma unroll
    for (int mi = 0; mi < 4; mi++) {
        int arow = warp_m * 64 + mi * 16 + (lane & 15);
        a_off[mi] = (uint32_t)(arow * ST + (lane >> 4) * 8) * 2u;
    }
    uint32_t b_off[2];
    #pragma unroll
    for (int nip = 0; nip < 2; nip++) {
        int nrow = warp_n * 32 + nip * 16 + ((lane >> 4) & 1) * 8 + (lane & 7);
        b_off[nip] = (uint32_t)(nrow * ST + ((lane >> 3) & 1) * 8) * 2u;
    }

    float acc[4][4][4];
    #pragma unroll
    for (int i = 0; i < 4; i++)
        #pragma unroll
        for (int j = 0; j < 4; j++)
            #pragma unroll
            for (int q = 0; q < 4; q++) acc[i][j][q] = 0.f;

    #pragma unroll
    for (int pc = 0; pc < 2; pc++) {
        uint32_t bb = sb + pc * (BUF_H * 2);
        load_tile_mma(bb + 0 * TILE_H * 2, Ahi, m0, pc, tid);
        load_tile_mma(bb + 1 * TILE_H * 2, Alo, m0, pc, tid);
        load_tile_mma(bb + 2 * TILE_H * 2, Whi, n0, pc, tid);
        load_tile_mma(bb + 3 * TILE_H * 2, Wlo, n0, pc, tid);
        CP_COMMIT();
    }

    #pragma unroll 1
    for (int kc = 0; kc < NCH; kc++) {
        uint32_t bb = sb + (kc & 1) * (BUF_H * 2);
        if (kc < NCH - 1) CP_WAIT(1); else CP_WAIT(0);
        __syncthreads();

        uint32_t Ah = bb, Al = bb + TILE_H * 2, Wh = bb + 2 * TILE_H * 2, Wl = bb + 3 * TILE_H * 2;
        #pragma unroll
        for (int ks = 0; ks < 2; ks++) {
            uint32_t koff = ks * 32;
            uint32_t ah[4][4], al[4][4], bh[2][4], bl[2][4];
            #pragma unroll
            for (int mi = 0; mi < 4; mi++) {
                LDSM_X4(ah[mi], Ah + a_off[mi] + koff);
                LDSM_X4(al[mi], Al + a_off[mi] + koff);
            }
            #pragma unroll
            for (int nip = 0; nip < 2; nip++) {
                LDSM_X4(bh[nip], Wh + b_off[nip] + koff);
                LDSM_X4(bl[nip], Wl + b_off[nip] + koff);
            }
            #pragma unroll
            for (int mi = 0; mi < 4; mi++) {
                #pragma unroll
                for (int ni = 0; ni < 4; ni++) {
                    int nip = ni >> 1, hf = (ni & 1) * 2;
                    MMA16816(acc[mi][ni], ah[mi], bh[nip][hf], bh[nip][hf + 1]);
                    MMA16816(acc[mi][ni], ah[mi], bl[nip][hf], bl[nip][hf + 1]);
                    MMA16816(acc[mi][ni], al[mi], bh[nip][hf], bh[nip][hf + 1]);
                }
            }
        }
        __syncthreads();
        if (kc + 2 < NCH) {
            load_tile_mma(bb + 0 * TILE_H * 2, Ahi, m0, kc + 2, tid);
            load_tile_mma(bb + 1 * TILE_H * 2, Alo, m0, kc + 2, tid);
            load_tile_mma(bb + 2 * TILE_H * 2, Whi, n0, kc + 2, tid);
            load_tile_mma(bb + 3 * TILE_H * 2, Wlo, n0, kc + 2, tid);
            CP_COMMIT();
        }
    }

    int rbase = m0 + warp_m * 64 + (lane >> 2);
    int cbase = n0 + warp_n * 32 + (lane & 3) * 2;
    #pragma unroll
    for (int mi = 0; mi < 4; mi++) {
        #pragma unroll
        for (int ni = 0; ni < 4; ni++) {
            int c = cbase + ni * 8;
            float b0 = bias[c], b1 = bias[c + 1];
            #pragma unroll
            for (int half = 0; half < 2; half++) {
                int r = rbase + mi * 16 + half * 8;
                float v0 = (acc[mi][ni][half * 2 + 0] + b0) * scale;
                float v1 = (acc[mi][ni][half * 2 + 1] + b1) * scale;
                if (mode == 0) {
                    float2 v; v.x = v0; v.y = v1;
                    *(float2*)(outf + (size_t)r * 1024 + c) = v;
                } else {
                    int t = r >> 2, b = r & 3;
                    int h = c >> 6, d = c & 63;
                    size_t ad = ((size_t)(b * Hn + h) * Tn + t) * DHn + d;
                    __nv_bfloat16 h0 = __float2bfloat16(v0);
                    __nv_bfloat16 h1 = __float2bfloat16(v1);
                    *(__nv_bfloat162*)(ohi + ad) = __nv_bfloat162(h0, h1);
                    *(__nv_bfloat162*)(olo + ad) = __nv_bfloat162(
                        __float2bfloat16(v0 - __bfloat162float(h0)),
                        __float2bfloat16(v1 - __bfloat162float(h1)));
                }
            }
        }
    }
}

// ================= split fp32 -> bf16 hi/lo =================
__global__ void split_kernel(const float* __restrict__ src,
                             __nv_bfloat16* __restrict__ hi,
                             __nv_bfloat16* __restrict__ lo, int n) {
    int i = (blockIdx.x * blockDim.x + threadIdx.x) * 4;
    if (i >= n) return;
    float4 v = *(const float4*)(src + i);
    __nv_bfloat16 h0 = __float2bfloat16(v.x), h1 = __float2bfloat16(v.y);
    __nv_bfloat16 h2 = __float2bfloat16(v.z), h3 = __float2bfloat16(v.w);
    __nv_bfloat16 l0 = __float2bfloat16(v.x - __bfloat162float(h0));
    __nv_bfloat16 l1 = __float2bfloat16(v.y - __bfloat162float(h1));
    __nv_bfloat16 l2 = __float2bfloat16(v.z - __bfloat162float(h2));
    __nv_bfloat16 l3 = __float2bfloat16(v.w - __bfloat162float(h3));
    __nv_bfloat162* hp = (__nv_bfloat162*)(hi + i);
    __nv_bfloat162* lp = (__nv_bfloat162*)(lo + i);
    hp[0] = __nv_bfloat162(h0, h1); hp[1] = __nv_bfloat162(h2, h3);
    lp[0] = __nv_bfloat162(l0, l1); lp[1] = __nv_bfloat162(l2, l3);
}

// ---------------- pos-bias table ----------------
__global__ void posb_kernel(const float* __restrict__ rel_bias) {
    int idx = blockIdx.x * blockDim.x + threadIdx.x;
    if (idx >= RSPAN) return;
    int rp = idx - (Tn - 1);
    const int n = 16;
    const int max_exact = 8;
    int bucket = (rp > 0) ? n : 0;
    int arp = abs(rp);
    int add;
    if (arp < max_exact) {
        add = arp;
    } else {
        float v = (log2f((float)arp) - 3.0f) * 2.0f;
        add = max_exact + (int)v;
        if (add > n - 1) add = n - 1;
    }
    bucket += add;
    #pragma unroll
    for (int h = 0; h < Hn; h++)
        g_posb[h*RSPAN + idx] = rel_bias[bucket*Hn + h];
}

// ---------------- gate kernel ----------------
__global__ void gate_kernel(const float* __restrict__ query,
                            const float* __restrict__ grep_w,
                            const float* __restrict__ grep_b,
                            const float* __restrict__ grep_a) {
    int warp = blockIdx.x * (blockDim.x >> 5) + (threadIdx.x >> 5);
    int lane = threadIdx.x & 31;
    if (warp >= Bn*Hn*Tn) return;
    int t = warp % Tn;
    int h = (warp / Tn) % Hn;
    int b = warp / (Tn * Hn);
    const float* q = query + ((size_t)t*Bn + b)*En + h*DHn;
    float q0 = q[lane], q1 = q[lane + 32];
    float s0 = 0.f, s1 = 0.f;
    #pragma unroll
    for (int e = 0; e < 8; e++) {
        float p = q0 * grep_w[e*DHn + lane] + q1 * grep_w[e*DHn + lane + 32];
        #pragma unroll
        for (int o = 16; o; o >>= 1) p += __shfl_xor_sync(0xffffffffu, p, o);
        p += grep_b[e];
        if (e < 4) s0 += p; else s1 += p;
    }
    if (lane == 0) {
        float ga = 1.f / (1.f + __expf(-s0));
        float gb = 1.f / (1.f + __expf(-s1));
        g_gate[warp] = ga * (gb * grep_a[h] - 1.0f) + 2.0f;
    }
}

// ================= HMMA flash attention =================
// grid (T/128=8, H, B), 256 threads (8 warps x 16 q-rows). K tiles of 64 keys.
#define AST   72                 // smem row stride in halves
#define ATSZ  (64*AST*2)         // 9216 B per 64x64 bf16 tile
#define ABUF  (4*ATSZ)           // khi,klo,vhi,vlo = 36864 B
#define ASM_LS (2*ABUF)          // 73728: Ls[2][192] floats
#define ASM_GS (ASM_LS + 2*192*4)
#define ASM_TOTAL (ASM_GS + 512)

__device__ __forceinline__ void attn_load_kv(uint32_t bbase,
        const __nv_bfloat16* kh, const __nv_bfloat16* kl,
        const __nv_bfloat16* vh, const __nv_bfloat16* vl, int s0, int tid) {
    #pragma unroll
    for (int it = 0; it < 2; it++) {
        int idx = tid + it * 256;
        int row = idx >> 3, seg = idx & 7;
        uint32_t doff = (uint32_t)row * 144 + seg * 16;
        size_t goff = (size_t)(s0 + row) * 64 + seg * 8;
        cpa16(bbase + 0*ATSZ + doff, kh + goff);
        cpa16(bbase + 1*ATSZ + doff, kl + goff);
        cpa16(bbase + 2*ATSZ + doff, vh + goff);
        cpa16(bbase + 3*ATSZ + doff, vl + goff);
    }
}

__global__ void __launch_bounds__(256, 1) attn_mma() {
    extern __shared__ char smraw[];
    uint32_t sb = smem_u32(smraw);
    float* Lsf = (float*)(smraw + ASM_LS);
    float* gsf = (float*)(smraw + ASM_GS);
    const int tid = threadIdx.x, wid = tid >> 5, lane = tid & 31;
    const int t0 = blockIdx.x * 128;
    const int h = blockIdx.y, b = blockIdx.z;
    const size_t hoff = (size_t)(b*Hn + h) * Tn * DHn;
    const __nv_bfloat16 *qhg = g_qhi + hoff, *qlg = g_qlo + hoff;
    const __nv_bfloat16 *khg = g_khi + hoff, *klg = g_klo + hoff;
    const __nv_bfloat16 *vhg = g_vhi + hoff, *vlg = g_vlo + hoff;

    // ---- Q staging (reuses K/V buffer region) ----
    #pragma unroll
    for (int it = 0; it < 4; it++) {
        int idx = tid + it * 256;
        int row = idx >> 3, seg = idx & 7;
        uint32_t doff = (uint32_t)row * 144 + seg * 16;
        size_t goff = (size_t)(t0 + row) * 64 + seg * 8;
        cpa16(sb + doff, qhg + goff);
        cpa16(sb + 18432 + doff, qlg + goff);
    }
    CP_COMMIT(); CP_WAIT(0); __syncthreads();

    uint32_t qfh[4][4], qfl[4][4];
    {
        int arow = wid * 16 + (lane & 15);
        #pragma unroll
        for (int kt = 0; kt < 4; kt++) {
            uint32_t aoff = (uint32_t)arow * 144 + ((uint32_t)kt * 16 + (lane >> 4) * 8) * 2;
            LDSM_X4(qfh[kt], sb + aoff);
            LDSM_X4(qfl[kt], sb + 18432 + aoff);
        }
    }
    if (tid < 128) gsf[tid] = g_gate[(b*Hn + h)*Tn + t0 + tid];
    __syncthreads();

    // pipeline prologue: K-tiles 0,1
    attn_load_kv(sb + 0*ABUF, khg, klg, vhg, vlg, 0, tid);  CP_COMMIT();
    attn_load_kv(sb + 1*ABUF, khg, klg, vhg, vlg, 64, tid); CP_COMMIT();
    if (tid < 191) {
        Lsf[tid]       = g_posb[h*RSPAN + 1023 + (0   - t0) + tid - 127];
        Lsf[192 + tid] = g_posb[h*RSPAN + 1023 + (64  - t0) + tid - 127];
    }

    float O[8][4];
    #pragma unroll
    for (int j = 0; j < 8; j++) { O[j][0]=0.f; O[j][1]=0.f; O[j][2]=0.f; O[j][3]=0.f; }
    float m0r = -1e30f, m1r = -1e30f, l0r = 0.f, l1r = 0.f;

    const int r0l = wid * 16 + (lane >> 2);     // local q row (and +8)
    const int cb  = (lane & 3) * 2;

    #pragma unroll 1
    for (int st = 0; st < 16; st++) {
        uint32_t bb = sb + (st & 1) * ABUF;
        float* Lss = Lsf + (st & 1) * 192;
        if (st < 15) CP_WAIT(1); else CP_WAIT(0);
        __syncthreads();

        // ---- S = Q K^T (3-term split) ----
        float S[8][4];
        #pragma unroll
        for (int j = 0; j < 8; j++) { S[j][0]=0.f; S[j][1]=0.f; S[j][2]=0.f; S[j][3]=0.f; }
        #pragma unroll
        for (int kt = 0; kt < 4; kt++) {
            #pragma unroll
            for (int nip = 0; nip < 4; nip++) {
                uint32_t boff = ((uint32_t)(nip*16 + ((lane>>4)&1)*8 + (lane&7))) * 144
                              + ((uint32_t)(kt*16 + ((lane>>3)&1)*8)) * 2;
                uint32_t bh[4], bl[4];
                LDSM_X4(bh, bb + boff);
                LDSM_X4(bl, bb + ATSZ + boff);
                #pragma unroll
                for (int hf = 0; hf < 2; hf++) {
                    int j = nip*2 + hf;
                    MMA16816(S[j], qfh[kt], bh[hf*2], bh[hf*2+1]);
                    MMA16816(S[j], qfh[kt], bl[hf*2], bl[hf*2+1]);
                    MMA16816(S[j], qfl[kt], bh[hf*2], bh[hf*2+1]);
                }
            }
        }

        // ---- bias ----
        float g0 = gsf[r0l], g1 = gsf[r0l + 8];
        int ib0 = 127 - r0l + cb;
        int ib1 = ib0 - 8;
        #pragma unroll
        for (int j = 0; j < 8; j++) {
            S[j][0] += g0 * Lss[ib0 + 8*j];
            S[j][1] += g0 * Lss[ib0 + 8*j + 1];
            S[j][2] += g1 * Lss[ib1 + 8*j];
            S[j][3] += g1 * Lss[ib1 + 8*j + 1];
        }

        // ---- online softmax (rows r0l, r0l+8) ----
        {
            float tm = fmaxf(S[0][0], S[0][1]);
            #pragma unroll
            for (int j = 1; j < 8; j++) tm = fmaxf(tm, fmaxf(S[j][0], S[j][1]));
            tm = fmaxf(tm, __shfl_xor_sync(0xffffffffu, tm, 1));
            tm = fmaxf(tm, __shfl_xor_sync(0xffffffffu, tm, 2));
            float mn = fmaxf(m0r, tm);
            float corr = __expf(m0r - mn);
            m0r = mn;
            float rs = 0.f;
            #pragma unroll
            for (int j = 0; j < 8; j++) {
                S[j][0] = __expf(S[j][0] - mn);
                S[j][1] = __expf(S[j][1] - mn);
                rs += S[j][0] + S[j][1];
            }
            rs += __shfl_xor_sync(0xffffffffu, rs, 1);
            rs += __shfl_xor_sync(0xffffffffu, rs, 2);
            l0r = l0r * corr + rs;
            #pragma unroll
            for (int j = 0; j < 8; j++) { O[j][0] *= corr; O[j][1] *= corr; }
        }
        {
            float tm = fmaxf(S[0][2], S[0][3]);
            #pragma unroll
            for (int j = 1; j < 8; j++) tm = fmaxf(tm, fmaxf(S[j][2], S[j][3]));
            tm = fmaxf(tm, __shfl_xor_sync(0xffffffffu, tm, 1));
            tm = fmaxf(tm, __shfl_xor_sync(0xffffffffu, tm, 2));
            float mn = fmaxf(m1r, tm);
            float corr = __expf(m1r - mn);
            m1r = mn;
            float rs = 0.f;
            #pragma unroll
            for (int j = 0; j < 8; j++) {
                S[j][2] = __expf(S[j][2] - mn);
                S[j][3] = __expf(S[j][3] - mn);
                rs += S[j][2] + S[j][3];
            }
            rs += __shfl_xor_sync(0xffffffffu, rs, 1);
            rs += __shfl_xor_sync(0xffffffffu, rs, 2);
            l1r = l1r * corr + rs;
            #pragma unroll
            for (int j = 0; j < 8; j++) { O[j][2] *= corr; O[j][3] *= corr; }
        }

        // ---- O += P V (3-term split, V via trans-ldmatrix) ----
        #pragma unroll
        for (int kt = 0; kt < 4; kt++) {
            uint32_t ph[4], pl[4];
            {
                float p00 = S[2*kt][0],   p01 = S[2*kt][1];
                float p02 = S[2*kt][2],   p03 = S[2*kt][3];
                float p10 = S[2*kt+1][0], p11 = S[2*kt+1][1];
                float p12 = S[2*kt+1][2], p13 = S[2*kt+1][3];
                ph[0] = pack_bf16x2(p00, p01);
                ph[1] = pack_bf16x2(p02, p03);
                ph[2] = pack_bf16x2(p10, p11);
                ph[3] = pack_bf16x2(p12, p13);
                pl[0] = pack_bf16x2(p00 - bf16_rt(p00), p01 - bf16_rt(p01));
                pl[1] = pack_bf16x2(p02 - bf16_rt(p02), p03 - bf16_rt(p03));
                pl[2] = pack_bf16x2(p10 - bf16_rt(p10), p11 - bf16_rt(p11));
                pl[3] = pack_bf16x2(p12 - bf16_rt(p12), p13 - bf16_rt(p13));
            }
            #pragma unroll
            for (int g = 0; g < 4; g++) {
                uint32_t voff = ((uint32_t)(kt*16 + (lane & 15))) * 144
                              + ((uint32_t)(g*16 + (lane >> 4) * 8)) * 2;
                uint32_t vh[4], vl[4];
                LDSM_X4_T(vh, bb + 2*ATSZ + voff);
                LDSM_X4_T(vl, bb + 3*ATSZ + voff);
                MMA16816(O[2*g],   ph, vh[0], vh[1]);
                MMA16816(O[2*g],   pl, vh[0], vh[1]);
                MMA16816(O[2*g],   ph, vl[0], vl[1]);
                MMA16816(O[2*g+1], ph, vh[2], vh[3]);
                MMA16816(O[2*g+1], pl, vh[2], vh[3]);
                MMA16816(O[2*g+1], ph, vl[2], vl[3]);
            }
        }

        __syncthreads();
        if (st + 2 < 16) {
            int s0n = (st + 2) * 64;
            attn_load_kv(sb + (st & 1) * ABUF, khg, klg, vhg, vlg, s0n, tid);
            CP_COMMIT();
            if (tid < 191)
                Lsf[(st & 1) * 192 + tid] = g_posb[h*RSPAN + 1023 + (s0n - t0) + tid - 127];
        }
    }

    // ---- epilogue: ctx as bf16 hi/lo into out-proj input ----
    float inv0 = 1.f / l0r, inv1 = 1.f / l1r;
    int tg0 = t0 + r0l;
    #pragma unroll
    for (int j = 0; j < 8; j++) {
        int d = h * 64 + 8*j + cb;
        {
            float v0 = O[j][0] * inv0, v1 = O[j][1] * inv0;
            __nv_bfloat16 h0 = __float2bfloat16(v0), h1 = __float2bfloat16(v1);
            size_t ad = ((size_t)tg0 * Bn + b) * En + d;
            *(__nv_bfloat162*)(g_xhi + ad) = __nv_bfloat162(h0, h1);
            *(__nv_bfloat162*)(g_xlo + ad) = __nv_bfloat162(
                __float2bfloat16(v0 - __bfloat162float(h0)),
                __float2bfloat16(v1 - __bfloat162float(h1)));
        }
        {
            float v0 = O[j][2] * inv1, v1 = O[j][3] * inv1;
            __nv_bfloat16 h0 = __float2bfloat16(v0), h1 = __float2bfloat16(v1);
            size_t ad = ((size_t)(tg0 + 8) * Bn + b) * En + d;
            *(__nv_bfloat162*)(g_xhi + ad) = __nv_bfloat162(h0, h1);
            *(__nv_bfloat162*)(g_xlo + ad) = __nv_bfloat162(
                __float2bfloat16(v0 - __bfloat162float(h0)),
                __float2bfloat16(v1 - __bfloat162float(h1)));
        }
    }
}

// ---------------- launch ----------------
extern "C" void kernel_launch(void* const* d_in, const int* in_sizes, int n_in,
                              void* d_out, int out_size) {
    const float* query  = (const float*)d_in[0];
    const float* q_w    = (const float*)d_in[1];
    const float* q_b    = (const float*)d_in[2];
    const float* k_w    = (const float*)d_in[3];
    const float* k_b    = (const float*)d_in[4];
    const float* v_w    = (const float*)d_in[5];
    const float* v_b    = (const float*)d_in[6];
    const float* out_w  = (const float*)d_in[7];
    const float* out_b  = (const float*)d_in[8];
    const float* rel_bias = (const float*)d_in[9];
    const float* grep_w = (const float*)d_in[10];
    const float* grep_b = (const float*)d_in[11];
    const float* grep_a = (const float*)d_in[12];
    float* out = (float*)d_out;

    __nv_bfloat16 *p_xhi, *p_xlo, *p_whi, *p_wlo;
    __nv_bfloat16 *p_qhi, *p_qlo, *p_khi, *p_klo, *p_vhi, *p_vlo;
    cudaGetSymbolAddress((void**)&p_xhi, g_xhi);
    cudaGetSymbolAddress((void**)&p_xlo, g_xlo);
    cudaGetSymbolAddress((void**)&p_whi, g_whi);
    cudaGetSymbolAddress((void**)&p_wlo, g_wlo);
    cudaGetSymbolAddress((void**)&p_qhi, g_qhi);
    cudaGetSymbolAddress((void**)&p_qlo, g_qlo);
    cudaGetSymbolAddress((void**)&p_khi, g_khi);
    cudaGetSymbolAddress((void**)&p_klo, g_klo);
    cudaGetSymbolAddress((void**)&p_vhi, g_vhi);
    cudaGetSymbolAddress((void**)&p_vlo, g_vlo);

    cudaFuncSetAttribute(gemm_mma, cudaFuncAttributeMaxDynamicSharedMemorySize, SMEM_G);
    cudaFuncSetAttribute(attn_mma, cudaFuncAttributeMaxDynamicSharedMemorySize, ASM_TOTAL);

    posb_kernel<<<(RSPAN + 255)/256, 256>>>(rel_bias);
    gate_kernel<<<(Bn*Hn*Tn)/4, 128>>>(query, grep_w, grep_b, grep_a);

    const int NA = Tn*Bn*En;
    const int NW = En*En;
    split_kernel<<<NA/1024, 256>>>(query, p_xhi, p_xlo, NA);
    split_kernel<<<NW/1024, 256>>>(q_w,   p_whi + 0*(size_t)NW, p_wlo + 0*(size_t)NW, NW);
    split_kernel<<<NW/1024, 256>>>(k_w,   p_whi + 1*(size_t)NW, p_wlo + 1*(size_t)NW, NW);
    split_kernel<<<NW/1024, 256>>>(v_w,   p_whi + 2*(size_t)NW, p_wlo + 2*(size_t)NW, NW);
    split_kernel<<<NW/1024, 256>>>(out_w, p_whi + 3*(size_t)NW, p_wlo + 3*(size_t)NW, NW);

    dim3 gg(En/128, (Tn*Bn)/128);   // (8, 32)
    const float scaling = 0.125f;   // DH^-0.5
    gemm_mma<<<gg, 256, SMEM_G>>>(p_xhi, p_xlo, p_whi + 0*(size_t)NW, p_wlo + 0*(size_t)NW,
                                  q_b, nullptr, p_qhi, p_qlo, scaling, 1);
    gemm_mma<<<gg, 256, SMEM_G>>>(p_xhi, p_xlo, p_whi + 1*(size_t)NW, p_wlo + 1*(size_t)NW,
                                  k_b, nullptr, p_khi, p_klo, 1.0f, 1);
    gemm_mma<<<gg, 256, SMEM_G>>>(p_xhi, p_xlo, p_whi + 2*(size_t)NW, p_wlo + 2*(size_t)NW,
                                  v_b, nullptr, p_vhi, p_vlo, 1.0f, 1);

    dim3 ga(Tn/128, Hn, Bn);        // (8, 16, 4)
    attn_mma<<<ga, 256, ASM_TOTAL>>>();

    gemm_mma<<<gg, 256, SMEM_G>>>(p_xhi, p_xlo, p_whi + 3*(size_t)NW, p_wlo + 3*(size_t)NW,
                                  out_b, out, nullptr, nullptr, 1.0f, 0);

    (void)in_sizes; (void)n_in; (void)out_size;
}

// round 5
// speedup vs baseline: 3.0305x; 1.0453x over previous
#include <cuda_runtime.h>
#include <cuda_bf16.h>
#include <math.h>
#include <cstdint>

#define Tn 1024
#define Bn 4
#define En 1024
#define Hn 16
#define DHn 64
#define RSPAN (2*Tn - 1)   // 2047

// ---------------- scratch ----------------
__device__ float g_gate[Bn*Hn*Tn];
__device__ float g_posb[Hn*RSPAN];

__device__ __nv_bfloat16 g_xhi[(size_t)Tn*Bn*En];   // activations (query split / ctx)
__device__ __nv_bfloat16 g_xlo[(size_t)Tn*Bn*En];
__device__ __nv_bfloat16 g_whi[4][(size_t)En*En];   // q_w,k_w,v_w,out_w
__device__ __nv_bfloat16 g_wlo[4][(size_t)En*En];

__device__ __nv_bfloat16 g_qhi[(size_t)Bn*Hn*Tn*DHn];  // [B,H,T,DH]
__device__ __nv_bfloat16 g_qlo[(size_t)Bn*Hn*Tn*DHn];
__device__ __nv_bfloat16 g_khi[(size_t)Bn*Hn*Tn*DHn];
__device__ __nv_bfloat16 g_klo[(size_t)Bn*Hn*Tn*DHn];
__device__ __nv_bfloat16 g_vhi[(size_t)Bn*Hn*Tn*DHn];
__device__ __nv_bfloat16 g_vlo[(size_t)Bn*Hn*Tn*DHn];

// ================= helpers =================
__device__ __forceinline__ uint32_t smem_u32(const void* p) {
    uint32_t a;
    asm("{ .reg .u64 t; cvta.to.shared.u64 t, %1; cvt.u32.u64 %0, t; }" : "=r"(a) : "l"(p));
    return a;
}
__device__ __forceinline__ void cpa16(uint32_t dst, const void* src) {
    asm volatile("cp.async.cg.shared.global [%0], [%1], 16;" :: "r"(dst), "l"(src));
}
#define CP_COMMIT() asm volatile("cp.async.commit_group;" ::: "memory")
#define CP_WAIT(n)  asm volatile("cp.async.wait_group %0;" :: "n"(n) : "memory")

#define LDSM_X4(r, a) \
    asm volatile("ldmatrix.sync.aligned.m8n8.x4.shared.b16 {%0,%1,%2,%3}, [%4];" \
        : "=r"((r)[0]), "=r"((r)[1]), "=r"((r)[2]), "=r"((r)[3]) : "r"(a))
#define LDSM_X4_T(r, a) \
    asm volatile("ldmatrix.sync.aligned.m8n8.x4.trans.shared.b16 {%0,%1,%2,%3}, [%4];" \
        : "=r"((r)[0]), "=r"((r)[1]), "=r"((r)[2]), "=r"((r)[3]) : "r"(a))

#define MMA16816(c, a, b0, b1) \
    asm volatile("mma.sync.aligned.m16n8k16.row.col.f32.bf16.bf16.f32 " \
        "{%0,%1,%2,%3}, {%4,%5,%6,%7}, {%8,%9}, {%0,%1,%2,%3};" \
        : "+f"((c)[0]), "+f"((c)[1]), "+f"((c)[2]), "+f"((c)[3]) \
        : "r"((a)[0]), "r"((a)[1]), "r"((a)[2]), "r"((a)[3]), "r"(b0), "r"(b1))

__device__ __forceinline__ uint32_t pack_bf16x2(float lo, float hi) {
    uint32_t r;
    asm("cvt.rn.bf16x2.f32 %0, %1, %2;" : "=r"(r) : "f"(hi), "f"(lo));
    return r;
}
__device__ __forceinline__ float bf16_rt(float x) {
    return __bfloat162float(__float2bfloat16(x));
}

// ================= HMMA bf16-split GEMM (3-stage pipeline) =================
#define ST 40
#define TILE_H (128*ST)          // halves per 128x32 tile
#define BUF_B  (4*TILE_H*2)      // bytes per stage: Ahi,Alo,Whi,Wlo = 40960
#define SMEM_G (3*BUF_B)         // 122880
#define NCH 32

__device__ __forceinline__ void load_tile_mma(uint32_t sdst, const __nv_bfloat16* g,
                                              int r0, int kc, int tid) {
    #pragma unroll
    for (int it = 0; it < 2; it++) {
        int idx = tid + it * 256;
        int row = idx >> 2, seg = idx & 3;
        uint32_t dst = sdst + (uint32_t)(row * ST) * 2u + seg * 16;
        const char* src = (const char*)(g + (size_t)(r0 + row) * 1024 + kc * 32 + seg * 8);
        cpa16(dst, src);
    }
}
__device__ __forceinline__ void load_stage(uint32_t bb,
        const __nv_bfloat16* Ahi, const __nv_bfloat16* Alo,
        const __nv_bfloat16* Whi, const __nv_bfloat16* Wlo,
        int m0, int n0, int kc, int tid) {
    load_tile_mma(bb + 0 * TILE_H * 2, Ahi, m0, kc, tid);
    load_tile_mma(bb + 1 * TILE_H * 2, Alo, m0, kc, tid);
    load_tile_mma(bb + 2 * TILE_H * 2, Whi, n0, kc, tid);
    load_tile_mma(bb + 3 * TILE_H * 2, Wlo, n0, kc, tid);
    CP_COMMIT();
}

// shared mainloop: accumulates acc[4][4][4] for this warp
__device__ __forceinline__ void gemm_mainloop(uint32_t sb,
        const __nv_bfloat16* Ahi, const __nv_bfloat16* Alo,
        const __nv_bfloat16* Whi, const __nv_bfloat16* Wlo,
        int m0, int n0, int tid, int wid, int lane, float acc[4][4][4]) {
    int warp_m = wid & 1;
    int warp_n = wid >> 1;
    uint32_t a_off[4];
    #pragma unroll
    for (int mi = 0; mi < 4; mi++) {
        int arow = warp_m * 64 + mi * 16 + (lane & 15);
        a_off[mi] = (uint32_t)(arow * ST + (lane >> 4) * 8) * 2u;
    }
    uint32_t b_off[2];
    #pragma unroll
    for (int nip = 0; nip < 2; nip++) {
        int nrow = warp_n * 32 + nip * 16 + ((lane >> 4) & 1) * 8 + (lane & 7);
        b_off[nip] = (uint32_t)(nrow * ST + ((lane >> 3) & 1) * 8) * 2u;
    }

    load_stage(sb + 0 * BUF_B, Ahi, Alo, Whi, Wlo, m0, n0, 0, tid);
    load_stage(sb + 1 * BUF_B, Ahi, Alo, Whi, Wlo, m0, n0, 1, tid);

    int stage = 0, nstage = 2;
    #pragma unroll 1
    for (int kc = 0; kc < NCH; kc++) {
        if (kc < NCH - 1) CP_WAIT(1); else CP_WAIT(0);
        __syncthreads();
        if (kc + 2 < NCH) {
            load_stage(sb + nstage * BUF_B, Ahi, Alo, Whi, Wlo, m0, n0, kc + 2, tid);
            nstage = (nstage == 2) ? 0 : nstage + 1;
        }
        uint32_t bb = sb + stage * BUF_B;
        stage = (stage == 2) ? 0 : stage + 1;
        uint32_t Ah = bb, Al = bb + TILE_H * 2, Wh = bb + 2 * TILE_H * 2, Wl = bb + 3 * TILE_H * 2;
        #pragma unroll
        for (int ks = 0; ks < 2; ks++) {
            uint32_t koff = ks * 32;
            uint32_t ah[4][4], al[4][4], bh[2][4], bl[2][4];
            #pragma unroll
            for (int mi = 0; mi < 4; mi++) {
                LDSM_X4(ah[mi], Ah + a_off[mi] + koff);
                LDSM_X4(al[mi], Al + a_off[mi] + koff);
            }
            #pragma unroll
            for (int nip = 0; nip < 2; nip++) {
                LDSM_X4(bh[nip], Wh + b_off[nip] + koff);
                LDSM_X4(bl[nip], Wl + b_off[nip] + koff);
            }
            #pragma unroll
            for (int mi = 0; mi < 4; mi++) {
                #pragma unroll
                for (int ni = 0; ni < 4; ni++) {
                    int nip = ni >> 1, hf = (ni & 1) * 2;
                    MMA16816(acc[mi][ni], ah[mi], bh[nip][hf], bh[nip][hf + 1]);
                    MMA16816(acc[mi][ni], ah[mi], bl[nip][hf], bl[nip][hf + 1]);
                    MMA16816(acc[mi][ni], al[mi], bh[nip][hf], bh[nip][hf + 1]);
                }
            }
        }
    }
}

// fused QKV: grid (24, 32). blockIdx.x>>3 selects {q,k,v}.
__global__ void __launch_bounds__(256, 1)
gemm_qkv(const __nv_bfloat16* __restrict__ Ahi, const __nv_bfloat16* __restrict__ Alo,
         const float* __restrict__ q_b, const float* __restrict__ k_b,
         const float* __restrict__ v_b) {
    extern __shared__ char smraw[];
    uint32_t sb = smem_u32(smraw);
    int tid = threadIdx.x, wid = tid >> 5, lane = tid & 31;
    int w = blockIdx.x >> 3;
    int n0 = (blockIdx.x & 7) * 128, m0 = blockIdx.y * 128;

    const size_t NW = (size_t)En * En;
    const __nv_bfloat16* Whi = &g_whi[0][0] + (size_t)w * NW;
    const __nv_bfloat16* Wlo = &g_wlo[0][0] + (size_t)w * NW;
    const float* bias = (w == 0) ? q_b : (w == 1) ? k_b : v_b;
    __nv_bfloat16* ohi = (w == 0) ? g_qhi : (w == 1) ? g_khi : g_vhi;
    __nv_bfloat16* olo = (w == 0) ? g_qlo : (w == 1) ? g_klo : g_vlo;
    float scale = (w == 0) ? 0.125f : 1.0f;

    float acc[4][4][4];
    #pragma unroll
    for (int i = 0; i < 4; i++)
        #pragma unroll
        for (int j = 0; j < 4; j++)
            #pragma unroll
            for (int q = 0; q < 4; q++) acc[i][j][q] = 0.f;

    gemm_mainloop(sb, Ahi, Alo, Whi, Wlo, m0, n0, tid, wid, lane, acc);

    int rbase = m0 + (wid & 1) * 64 + (lane >> 2);
    int cbase = n0 + (wid >> 1) * 32 + (lane & 3) * 2;
    #pragma unroll
    for (int mi = 0; mi < 4; mi++) {
        #pragma unroll
        for (int ni = 0; ni < 4; ni++) {
            int c = cbase + ni * 8;
            float b0 = bias[c], b1 = bias[c + 1];
            #pragma unroll
            for (int half = 0; half < 2; half++) {
                int r = rbase + mi * 16 + half * 8;
                float v0 = (acc[mi][ni][half * 2 + 0] + b0) * scale;
                float v1 = (acc[mi][ni][half * 2 + 1] + b1) * scale;
                int t = r >> 2, b = r & 3;
                int h = c >> 6, d = c & 63;
                size_t ad = ((size_t)(b * Hn + h) * Tn + t) * DHn + d;
                __nv_bfloat16 h0 = __float2bfloat16(v0);
                __nv_bfloat16 h1 = __float2bfloat16(v1);
                *(__nv_bfloat162*)(ohi + ad) = __nv_bfloat162(h0, h1);
                *(__nv_bfloat162*)(olo + ad) = __nv_bfloat162(
                    __float2bfloat16(v0 - __bfloat162float(h0)),
                    __float2bfloat16(v1 - __bfloat162float(h1)));
            }
        }
    }
}

// out projection: fp32 row-major output
__global__ void __launch_bounds__(256, 1)
gemm_out(const __nv_bfloat16* __restrict__ Ahi, const __nv_bfloat16* __restrict__ Alo,
         const __nv_bfloat16* __restrict__ Whi, const __nv_bfloat16* __restrict__ Wlo,
         const float* __restrict__ bias, float* __restrict__ outf) {
    extern __shared__ char smraw[];
    uint32_t sb = smem_u32(smraw);
    int tid = threadIdx.x, wid = tid >> 5, lane = tid & 31;
    int n0 = blockIdx.x * 128, m0 = blockIdx.y * 128;

    float acc[4][4][4];
    #pragma unroll
    for (int i = 0; i < 4; i++)
        #pragma unroll
        for (int j = 0; j < 4; j++)
            #pragma unroll
            for (int q = 0; q < 4; q++) acc[i][j][q] = 0.f;

    gemm_mainloop(sb, Ahi, Alo, Whi, Wlo, m0, n0, tid, wid, lane, acc);

    int rbase = m0 + (wid & 1) * 64 + (lane >> 2);
    int cbase = n0 + (wid >> 1) * 32 + (lane & 3) * 2;
    #pragma unroll
    for (int mi = 0; mi < 4; mi++) {
        #pragma unroll
        for (int ni = 0; ni < 4; ni++) {
            int c = cbase + ni * 8;
            float b0 = bias[c], b1 = bias[c + 1];
            #pragma unroll
            for (int half = 0; half < 2; half++) {
                int r = rbase + mi * 16 + half * 8;
                float2 v;
                v.x = acc[mi][ni][half * 2 + 0] + b0;
                v.y = acc[mi][ni][half * 2 + 1] + b1;
                *(float2*)(outf + (size_t)r * 1024 + c) = v;
            }
        }
    }
}

// ================= split fp32 -> bf16 hi/lo =================
__global__ void split_kernel(const float* __restrict__ src,
                             __nv_bfloat16* __restrict__ hi,
                             __nv_bfloat16* __restrict__ lo, int n) {
    int i = (blockIdx.x * blockDim.x + threadIdx.x) * 4;
    if (i >= n) return;
    float4 v = *(const float4*)(src + i);
    __nv_bfloat16 h0 = __float2bfloat16(v.x), h1 = __float2bfloat16(v.y);
    __nv_bfloat16 h2 = __float2bfloat16(v.z), h3 = __float2bfloat16(v.w);
    __nv_bfloat16 l0 = __float2bfloat16(v.x - __bfloat162float(h0));
    __nv_bfloat16 l1 = __float2bfloat16(v.y - __bfloat162float(h1));
    __nv_bfloat16 l2 = __float2bfloat16(v.z - __bfloat162float(h2));
    __nv_bfloat16 l3 = __float2bfloat16(v.w - __bfloat162float(h3));
    __nv_bfloat162* hp = (__nv_bfloat162*)(hi + i);
    __nv_bfloat162* lp = (__nv_bfloat162*)(lo + i);
    hp[0] = __nv_bfloat162(h0, h1); hp[1] = __nv_bfloat162(h2, h3);
    lp[0] = __nv_bfloat162(l0, l1); lp[1] = __nv_bfloat162(l2, l3);
}

// all 4 weights in one launch
__global__ void split_weights(const float* __restrict__ s0, const float* __restrict__ s1,
                              const float* __restrict__ s2, const float* __restrict__ s3) {
    const int NW = En * En;
    int i = (blockIdx.x * blockDim.x + threadIdx.x) * 4;
    int w = i / NW;
    int off = i - w * NW;
    const float* src = (w == 0) ? s0 : (w == 1) ? s1 : (w == 2) ? s2 : s3;
    float4 v = *(const float4*)(src + off);
    __nv_bfloat16 h0 = __float2bfloat16(v.x), h1 = __float2bfloat16(v.y);
    __nv_bfloat16 h2 = __float2bfloat16(v.z), h3 = __float2bfloat16(v.w);
    size_t gi = (size_t)w * NW + off;
    __nv_bfloat162* hp = (__nv_bfloat162*)(&g_whi[0][0] + gi);
    __nv_bfloat162* lp = (__nv_bfloat162*)(&g_wlo[0][0] + gi);
    hp[0] = __nv_bfloat162(h0, h1); hp[1] = __nv_bfloat162(h2, h3);
    lp[0] = __nv_bfloat162(__float2bfloat16(v.x - __bfloat162float(h0)),
                           __float2bfloat16(v.y - __bfloat162float(h1)));
    lp[1] = __nv_bfloat162(__float2bfloat16(v.z - __bfloat162float(h2)),
                           __float2bfloat16(v.w - __bfloat162float(h3)));
}

// ---------------- pos-bias table ----------------
__global__ void posb_kernel(const float* __restrict__ rel_bias) {
    int idx = blockIdx.x * blockDim.x + threadIdx.x;
    if (idx >= RSPAN) return;
    int rp = idx - (Tn - 1);
    const int n = 16;
    const int max_exact = 8;
    int bucket = (rp > 0) ? n : 0;
    int arp = abs(rp);
    int add;
    if (arp < max_exact) {
        add = arp;
    } else {
        float v = (log2f((float)arp) - 3.0f) * 2.0f;
        add = max_exact + (int)v;
        if (add > n - 1) add = n - 1;
    }
    bucket += add;
    #pragma unroll
    for (int h = 0; h < Hn; h++)
        g_posb[h*RSPAN + idx] = rel_bias[bucket*Hn + h];
}

// ---------------- gate kernel ----------------
__global__ void gate_kernel(const float* __restrict__ query,
                            const float* __restrict__ grep_w,
                            const float* __restrict__ grep_b,
                            const float* __restrict__ grep_a) {
    int warp = blockIdx.x * (blockDim.x >> 5) + (threadIdx.x >> 5);
    int lane = threadIdx.x & 31;
    if (warp >= Bn*Hn*Tn) return;
    int t = warp % Tn;
    int h = (warp / Tn) % Hn;
    int b = warp / (Tn * Hn);
    const float* q = query + ((size_t)t*Bn + b)*En + h*DHn;
    float q0 = q[lane], q1 = q[lane + 32];
    float s0 = 0.f, s1 = 0.f;
    #pragma unroll
    for (int e = 0; e < 8; e++) {
        float p = q0 * grep_w[e*DHn + lane] + q1 * grep_w[e*DHn + lane + 32];
        #pragma unroll
        for (int o = 16; o; o >>= 1) p += __shfl_xor_sync(0xffffffffu, p, o);
        p += grep_b[e];
        if (e < 4) s0 += p; else s1 += p;
    }
    if (lane == 0) {
        float ga = 1.f / (1.f + __expf(-s0));
        float gb = 1.f / (1.f + __expf(-s1));
        g_gate[warp] = ga * (gb * grep_a[h] - 1.0f) + 2.0f;
    }
}

// ================= HMMA flash attention (3-stage pipeline) =================
#define ATSZ  (64*72*2)          // 9216 B per 64x64 bf16 tile (stride 144B)
#define ABUF  (4*ATSZ)           // khi,klo,vhi,vlo = 36864 B per stage
#define ASM_LS (3*ABUF)          // 110592
#define ASM_GS (ASM_LS + 3*192*4)
#define ASM_TOTAL (ASM_GS + 512)
#define NTILE 16

__device__ __forceinline__ void attn_load_kv(uint32_t bbase,
        const __nv_bfloat16* kh, const __nv_bfloat16* kl,
        const __nv_bfloat16* vh, const __nv_bfloat16* vl, int s0, int tid) {
    #pragma unroll
    for (int it = 0; it < 2; it++) {
        int idx = tid + it * 256;
        int row = idx >> 3, seg = idx & 7;
        uint32_t doff = (uint32_t)row * 144 + seg * 16;
        size_t goff = (size_t)(s0 + row) * 64 + seg * 8;
        cpa16(bbase + 0*ATSZ + doff, kh + goff);
        cpa16(bbase + 1*ATSZ + doff, kl + goff);
        cpa16(bbase + 2*ATSZ + doff, vh + goff);
        cpa16(bbase + 3*ATSZ + doff, vl + goff);
    }
    CP_COMMIT();
}

__global__ void __launch_bounds__(256, 1) attn_mma() {
    extern __shared__ char smraw[];
    uint32_t sb = smem_u32(smraw);
    float* Lsf = (float*)(smraw + ASM_LS);
    float* gsf = (float*)(smraw + ASM_GS);
    const int tid = threadIdx.x, wid = tid >> 5, lane = tid & 31;
    const int t0 = blockIdx.x * 128;
    const int h = blockIdx.y, b = blockIdx.z;
    const size_t hoff = (size_t)(b*Hn + h) * Tn * DHn;
    const __nv_bfloat16 *qhg = g_qhi + hoff, *qlg = g_qlo + hoff;
    const __nv_bfloat16 *khg = g_khi + hoff, *klg = g_klo + hoff;
    const __nv_bfloat16 *vhg = g_vhi + hoff, *vlg = g_vlo + hoff;

    // ---- Q staging (uses stage-0 region) ----
    #pragma unroll
    for (int it = 0; it < 4; it++) {
        int idx = tid + it * 256;
        int row = idx >> 3, seg = idx & 7;
        uint32_t doff = (uint32_t)row * 144 + seg * 16;
        size_t goff = (size_t)(t0 + row) * 64 + seg * 8;
        cpa16(sb + doff, qhg + goff);
        cpa16(sb + 18432 + doff, qlg + goff);
    }
    CP_COMMIT(); CP_WAIT(0); __syncthreads();

    uint32_t qfh[4][4], qfl[4][4];
    {
        int arow = wid * 16 + (lane & 15);
        #pragma unroll
        for (int kt = 0; kt < 4; kt++) {
            uint32_t aoff = (uint32_t)arow * 144 + ((uint32_t)kt * 16 + (lane >> 4) * 8) * 2;
            LDSM_X4(qfh[kt], sb + aoff);
            LDSM_X4(qfl[kt], sb + 18432 + aoff);
        }
    }
    if (tid < 128) gsf[tid] = g_gate[(b*Hn + h)*Tn + t0 + tid];
    __syncthreads();

    // prologue: tiles 0,1 into stages 0,1
    attn_load_kv(sb + 0*ABUF, khg, klg, vhg, vlg, 0, tid);
    attn_load_kv(sb + 1*ABUF, khg, klg, vhg, vlg, 64, tid);
    if (tid < 191) {
        Lsf[tid]       = g_posb[h*RSPAN + 1023 + (0  - t0) + tid - 127];
        Lsf[192 + tid] = g_posb[h*RSPAN + 1023 + (64 - t0) + tid - 127];
    }

    float O[8][4];
    #pragma unroll
    for (int j = 0; j < 8; j++) { O[j][0]=0.f; O[j][1]=0.f; O[j][2]=0.f; O[j][3]=0.f; }
    float m0r = -1e30f, m1r = -1e30f, l0r = 0.f, l1r = 0.f;

    const int r0l = wid * 16 + (lane >> 2);
    const int cb  = (lane & 3) * 2;

    int stage = 0, nstage = 2;
    #pragma unroll 1
    for (int st = 0; st < NTILE; st++) {
        if (st < NTILE - 1) CP_WAIT(1); else CP_WAIT(0);
        __syncthreads();
        if (st + 2 < NTILE) {
            int s0n = (st + 2) * 64;
            attn_load_kv(sb + nstage * ABUF, khg, klg, vhg, vlg, s0n, tid);
            if (tid < 191)
                Lsf[nstage * 192 + tid] = g_posb[h*RSPAN + 1023 + (s0n - t0) + tid - 127];
            nstage = (nstage == 2) ? 0 : nstage + 1;
        }
        uint32_t bb = sb + stage * ABUF;
        float* Lss = Lsf + stage * 192;
        stage = (stage == 2) ? 0 : stage + 1;

        // ---- S = Q K^T (3-term split) ----
        float S[8][4];
        #pragma unroll
        for (int j = 0; j < 8; j++) { S[j][0]=0.f; S[j][1]=0.f; S[j][2]=0.f; S[j][3]=0.f; }
        #pragma unroll
        for (int kt = 0; kt < 4; kt++) {
            #pragma unroll
            for (int nip = 0; nip < 4; nip++) {
                uint32_t boff = ((uint32_t)(nip*16 + ((lane>>4)&1)*8 + (lane&7))) * 144
                              + ((uint32_t)(kt*16 + ((lane>>3)&1)*8)) * 2;
                uint32_t bh[4], bl[4];
                LDSM_X4(bh, bb + boff);
                LDSM_X4(bl, bb + ATSZ + boff);
                #pragma unroll
                for (int hf = 0; hf < 2; hf++) {
                    int j = nip*2 + hf;
                    MMA16816(S[j], qfh[kt], bh[hf*2], bh[hf*2+1]);
                    MMA16816(S[j], qfh[kt], bl[hf*2], bl[hf*2+1]);
                    MMA16816(S[j], qfl[kt], bh[hf*2], bh[hf*2+1]);
                }
            }
        }

        // ---- bias ----
        float g0 = gsf[r0l], g1 = gsf[r0l + 8];
        int ib0 = 127 - r0l + cb;
        int ib1 = ib0 - 8;
        #pragma unroll
        for (int j = 0; j < 8; j++) {
            S[j][0] += g0 * Lss[ib0 + 8*j];
            S[j][1] += g0 * Lss[ib0 + 8*j + 1];
            S[j][2] += g1 * Lss[ib1 + 8*j];
            S[j][3] += g1 * Lss[ib1 + 8*j + 1];
        }

        // ---- online softmax ----
        {
            float tm = fmaxf(S[0][0], S[0][1]);
            #pragma unroll
            for (int j = 1; j < 8; j++) tm = fmaxf(tm, fmaxf(S[j][0], S[j][1]));
            tm = fmaxf(tm, __shfl_xor_sync(0xffffffffu, tm, 1));
            tm = fmaxf(tm, __shfl_xor_sync(0xffffffffu, tm, 2));
            float mn = fmaxf(m0r, tm);
            float corr = __expf(m0r - mn);
            m0r = mn;
            float rs = 0.f;
            #pragma unroll
            for (int j = 0; j < 8; j++) {
                S[j][0] = __expf(S[j][0] - mn);
                S[j][1] = __expf(S[j][1] - mn);
                rs += S[j][0] + S[j][1];
            }
            rs += __shfl_xor_sync(0xffffffffu, rs, 1);
            rs += __shfl_xor_sync(0xffffffffu, rs, 2);
            l0r = l0r * corr + rs;
            #pragma unroll
            for (int j = 0; j < 8; j++) { O[j][0] *= corr; O[j][1] *= corr; }
        }
        {
            float tm = fmaxf(S[0][2], S[0][3]);
            #pragma unroll
            for (int j = 1; j < 8; j++) tm = fmaxf(tm, fmaxf(S[j][2], S[j][3]));
            tm = fmaxf(tm, __shfl_xor_sync(0xffffffffu, tm, 1));
            tm = fmaxf(tm, __shfl_xor_sync(0xffffffffu, tm, 2));
            float mn = fmaxf(m1r, tm);
            float corr = __expf(m1r - mn);
            m1r = mn;
            float rs = 0.f;
            #pragma unroll
            for (int j = 0; j < 8; j++) {
                S[j][2] = __expf(S[j][2] - mn);
                S[j][3] = __expf(S[j][3] - mn);
                rs += S[j][2] + S[j][3];
            }
            rs += __shfl_xor_sync(0xffffffffu, rs, 1);
            rs += __shfl_xor_sync(0xffffffffu, rs, 2);
            l1r = l1r * corr + rs;
            #pragma unroll
            for (int j = 0; j < 8; j++) { O[j][2] *= corr; O[j][3] *= corr; }
        }

        // ---- O += P V ----
        #pragma unroll
        for (int kt = 0; kt < 4; kt++) {
            uint32_t ph[4], pl[4];
            {
                float p00 = S[2*kt][0],   p01 = S[2*kt][1];
                float p02 = S[2*kt][2],   p03 = S[2*kt][3];
                float p10 = S[2*kt+1][0], p11 = S[2*kt+1][1];
                float p12 = S[2*kt+1][2], p13 = S[2*kt+1][3];
                ph[0] = pack_bf16x2(p00, p01);
                ph[1] = pack_bf16x2(p02, p03);
                ph[2] = pack_bf16x2(p10, p11);
                ph[3] = pack_bf16x2(p12, p13);
                pl[0] = pack_bf16x2(p00 - bf16_rt(p00), p01 - bf16_rt(p01));
                pl[1] = pack_bf16x2(p02 - bf16_rt(p02), p03 - bf16_rt(p03));
                pl[2] = pack_bf16x2(p10 - bf16_rt(p10), p11 - bf16_rt(p11));
                pl[3] = pack_bf16x2(p12 - bf16_rt(p12), p13 - bf16_rt(p13));
            }
            #pragma unroll
            for (int g = 0; g < 4; g++) {
                uint32_t voff = ((uint32_t)(kt*16 + (lane & 15))) * 144
                              + ((uint32_t)(g*16 + (lane >> 4) * 8)) * 2;
                uint32_t vh[4], vl[4];
                LDSM_X4_T(vh, bb + 2*ATSZ + voff);
                LDSM_X4_T(vl, bb + 3*ATSZ + voff);
                MMA16816(O[2*g],   ph, vh[0], vh[1]);
                MMA16816(O[2*g],   pl, vh[0], vh[1]);
                MMA16816(O[2*g],   ph, vl[0], vl[1]);
                MMA16816(O[2*g+1], ph, vh[2], vh[3]);
                MMA16816(O[2*g+1], pl, vh[2], vh[3]);
                MMA16816(O[2*g+1], ph, vl[2], vl[3]);
            }
        }
    }

    // ---- epilogue ----
    float inv0 = 1.f / l0r, inv1 = 1.f / l1r;
    int tg0 = t0 + r0l;
    #pragma unroll
    for (int j = 0; j < 8; j++) {
        int d = h * 64 + 8*j + cb;
        {
            float v0 = O[j][0] * inv0, v1 = O[j][1] * inv0;
            __nv_bfloat16 h0 = __float2bfloat16(v0), h1 = __float2bfloat16(v1);
            size_t ad = ((size_t)tg0 * Bn + b) * En + d;
            *(__nv_bfloat162*)(g_xhi + ad) = __nv_bfloat162(h0, h1);
            *(__nv_bfloat162*)(g_xlo + ad) = __nv_bfloat162(
                __float2bfloat16(v0 - __bfloat162float(h0)),
                __float2bfloat16(v1 - __bfloat162float(h1)));
        }
        {
            float v0 = O[j][2] * inv1, v1 = O[j][3] * inv1;
            __nv_bfloat16 h0 = __float2bfloat16(v0), h1 = __float2bfloat16(v1);
            size_t ad = ((size_t)(tg0 + 8) * Bn + b) * En + d;
            *(__nv_bfloat162*)(g_xhi + ad) = __nv_bfloat162(h0, h1);
            *(__nv_bfloat162*)(g_xlo + ad) = __nv_bfloat162(
                __float2bfloat16(v0 - __bfloat162float(h0)),
                __float2bfloat16(v1 - __bfloat162float(h1)));
        }
    }
}

// ---------------- launch ----------------
extern "C" void kernel_launch(void* const* d_in, const int* in_sizes, int n_in,
                              void* d_out, int out_size) {
    const float* query  = (const float*)d_in[0];
    const float* q_w    = (const float*)d_in[1];
    const float* q_b    = (const float*)d_in[2];
    const float* k_w    = (const float*)d_in[3];
    const float* k_b    = (const float*)d_in[4];
    const float* v_w    = (const float*)d_in[5];
    const float* v_b    = (const float*)d_in[6];
    const float* out_w  = (const float*)d_in[7];
    const float* out_b  = (const float*)d_in[8];
    const float* rel_bias = (const float*)d_in[9];
    const float* grep_w = (const float*)d_in[10];
    const float* grep_b = (const float*)d_in[11];
    const float* grep_a = (const float*)d_in[12];
    float* out = (float*)d_out;

    __nv_bfloat16 *p_xhi, *p_xlo, *p_whi, *p_wlo;
    cudaGetSymbolAddress((void**)&p_xhi, g_xhi);
    cudaGetSymbolAddress((void**)&p_xlo, g_xlo);
    cudaGetSymbolAddress((void**)&p_whi, g_whi);
    cudaGetSymbolAddress((void**)&p_wlo, g_wlo);

    cudaFuncSetAttribute(gemm_qkv, cudaFuncAttributeMaxDynamicSharedMemorySize, SMEM_G);
    cudaFuncSetAttribute(gemm_out, cudaFuncAttributeMaxDynamicSharedMemorySize, SMEM_G);
    cudaFuncSetAttribute(attn_mma, cudaFuncAttributeMaxDynamicSharedMemorySize, ASM_TOTAL);

    posb_kernel<<<(RSPAN + 255)/256, 256>>>(rel_bias);
    gate_kernel<<<(Bn*Hn*Tn)/4, 128>>>(query, grep_w, grep_b, grep_a);

    const int NA = Tn*Bn*En;
    const int NW = En*En;
    split_kernel<<<NA/1024, 256>>>(query, p_xhi, p_xlo, NA);
    split_weights<<<4*NW/1024, 256>>>(q_w, k_w, v_w, out_w);

    dim3 gq(24, (Tn*Bn)/128);
    gemm_qkv<<<gq, 256, SMEM_G>>>(p_xhi, p_xlo, q_b, k_b, v_b);

    dim3 ga(Tn/128, Hn, Bn);
    attn_mma<<<ga, 256, ASM_TOTAL>>>();

    dim3 gg(En/128, (Tn*Bn)/128);
    gemm_out<<<gg, 256, SMEM_G>>>(p_xhi, p_xlo, p_whi + 3*(size_t)NW, p_wlo + 3*(size_t)NW,
                                  out_b, out);

    (void)in_sizes; (void)n_in; (void)out_size;
}

// round 6
// speedup vs baseline: 3.0780x; 1.0157x over previous
#include <cuda_runtime.h>
#include <cuda_bf16.h>
#include <math.h>
#include <cstdint>

#define Tn 1024
#define Bn 4
#define En 1024
#define Hn 16
#define DHn 64
#define RSPAN (2*Tn - 1)   // 2047
#define LOG2E 1.4426950408889634f

// ---------------- scratch ----------------
__device__ float g_gate[Bn*Hn*Tn];
__device__ float g_posb[Hn*RSPAN];

__device__ __nv_bfloat16 g_xhi[(size_t)Tn*Bn*En];   // activations (query split / ctx)
__device__ __nv_bfloat16 g_xlo[(size_t)Tn*Bn*En];
__device__ __nv_bfloat16 g_whi[4][(size_t)En*En];   // q_w,k_w,v_w,out_w
__device__ __nv_bfloat16 g_wlo[4][(size_t)En*En];

__device__ __nv_bfloat16 g_qhi[(size_t)Bn*Hn*Tn*DHn];  // [B,H,T,DH]
__device__ __nv_bfloat16 g_qlo[(size_t)Bn*Hn*Tn*DHn];
__device__ __nv_bfloat16 g_khi[(size_t)Bn*Hn*Tn*DHn];
__device__ __nv_bfloat16 g_klo[(size_t)Bn*Hn*Tn*DHn];
__device__ __nv_bfloat16 g_vhi[(size_t)Bn*Hn*Tn*DHn];
__device__ __nv_bfloat16 g_vlo[(size_t)Bn*Hn*Tn*DHn];

// ================= helpers =================
__device__ __forceinline__ uint32_t smem_u32(const void* p) {
    uint32_t a;
    asm("{ .reg .u64 t; cvta.to.shared.u64 t, %1; cvt.u32.u64 %0, t; }" : "=r"(a) : "l"(p));
    return a;
}
__device__ __forceinline__ void cpa16(uint32_t dst, const void* src) {
    asm volatile("cp.async.cg.shared.global [%0], [%1], 16;" :: "r"(dst), "l"(src));
}
#define CP_COMMIT() asm volatile("cp.async.commit_group;" ::: "memory")
#define CP_WAIT(n)  asm volatile("cp.async.wait_group %0;" :: "n"(n) : "memory")

#define LDSM_X4(r, a) \
    asm volatile("ldmatrix.sync.aligned.m8n8.x4.shared.b16 {%0,%1,%2,%3}, [%4];" \
        : "=r"((r)[0]), "=r"((r)[1]), "=r"((r)[2]), "=r"((r)[3]) : "r"(a))
#define LDSM_X4_T(r, a) \
    asm volatile("ldmatrix.sync.aligned.m8n8.x4.trans.shared.b16 {%0,%1,%2,%3}, [%4];" \
        : "=r"((r)[0]), "=r"((r)[1]), "=r"((r)[2]), "=r"((r)[3]) : "r"(a))

#define MMA16816(c, a, b0, b1) \
    asm volatile("mma.sync.aligned.m16n8k16.row.col.f32.bf16.bf16.f32 " \
        "{%0,%1,%2,%3}, {%4,%5,%6,%7}, {%8,%9}, {%0,%1,%2,%3};" \
        : "+f"((c)[0]), "+f"((c)[1]), "+f"((c)[2]), "+f"((c)[3]) \
        : "r"((a)[0]), "r"((a)[1]), "r"((a)[2]), "r"((a)[3]), "r"(b0), "r"(b1))

__device__ __forceinline__ uint32_t pack_bf16x2(float lo, float hi) {
    uint32_t r;
    asm("cvt.rn.bf16x2.f32 %0, %1, %2;" : "=r"(r) : "f"(hi), "f"(lo));
    return r;
}
__device__ __forceinline__ float bf16_rt(float x) {
    return __bfloat162float(__float2bfloat16(x));
}

// ================= HMMA bf16-split GEMM (4-stage pipeline) =================
#define ST 40
#define TILE_H (128*ST)          // halves per 128x32 tile
#define BUF_B  (4*TILE_H*2)      // bytes per stage: Ahi,Alo,Whi,Wlo = 40960
#define SMEM_G (4*BUF_B)         // 163840
#define NCH 32

__device__ __forceinline__ void load_tile_mma(uint32_t sdst, const __nv_bfloat16* g,
                                              int r0, int kc, int tid) {
    #pragma unroll
    for (int it = 0; it < 2; it++) {
        int idx = tid + it * 256;
        int row = idx >> 2, seg = idx & 3;
        uint32_t dst = sdst + (uint32_t)(row * ST) * 2u + seg * 16;
        const char* src = (const char*)(g + (size_t)(r0 + row) * 1024 + kc * 32 + seg * 8);
        cpa16(dst, src);
    }
}
__device__ __forceinline__ void load_stage(uint32_t bb,
        const __nv_bfloat16* Ahi, const __nv_bfloat16* Alo,
        const __nv_bfloat16* Whi, const __nv_bfloat16* Wlo,
        int m0, int n0, int kc, int tid) {
    load_tile_mma(bb + 0 * TILE_H * 2, Ahi, m0, kc, tid);
    load_tile_mma(bb + 1 * TILE_H * 2, Alo, m0, kc, tid);
    load_tile_mma(bb + 2 * TILE_H * 2, Whi, n0, kc, tid);
    load_tile_mma(bb + 3 * TILE_H * 2, Wlo, n0, kc, tid);
    CP_COMMIT();
}

__device__ __forceinline__ void gemm_mainloop(uint32_t sb,
        const __nv_bfloat16* Ahi, const __nv_bfloat16* Alo,
        const __nv_bfloat16* Whi, const __nv_bfloat16* Wlo,
        int m0, int n0, int tid, int wid, int lane, float acc[4][4][4]) {
    int warp_m = wid & 1;
    int warp_n = wid >> 1;
    uint32_t a_off[4];
    #pragma unroll
    for (int mi = 0; mi < 4; mi++) {
        int arow = warp_m * 64 + mi * 16 + (lane & 15);
        a_off[mi] = (uint32_t)(arow * ST + (lane >> 4) * 8) * 2u;
    }
    uint32_t b_off[2];
    #pragma unroll
    for (int nip = 0; nip < 2; nip++) {
        int nrow = warp_n * 32 + nip * 16 + ((lane >> 4) & 1) * 8 + (lane & 7);
        b_off[nip] = (uint32_t)(nrow * ST + ((lane >> 3) & 1) * 8) * 2u;
    }

    load_stage(sb + 0 * BUF_B, Ahi, Alo, Whi, Wlo, m0, n0, 0, tid);
    load_stage(sb + 1 * BUF_B, Ahi, Alo, Whi, Wlo, m0, n0, 1, tid);
    load_stage(sb + 2 * BUF_B, Ahi, Alo, Whi, Wlo, m0, n0, 2, tid);

    #pragma unroll 1
    for (int kc = 0; kc < NCH; kc++) {
        if (kc <= NCH - 3)      CP_WAIT(2);
        else if (kc == NCH - 2) CP_WAIT(1);
        else                    CP_WAIT(0);
        __syncthreads();
        if (kc + 3 < NCH)
            load_stage(sb + ((kc + 3) & 3) * BUF_B, Ahi, Alo, Whi, Wlo, m0, n0, kc + 3, tid);
        uint32_t bb = sb + (kc & 3) * BUF_B;
        uint32_t Ah = bb, Al = bb + TILE_H * 2, Wh = bb + 2 * TILE_H * 2, Wl = bb + 3 * TILE_H * 2;
        #pragma unroll
        for (int ks = 0; ks < 2; ks++) {
            uint32_t koff = ks * 32;
            uint32_t ah[4][4], al[4][4], bh[2][4], bl[2][4];
            #pragma unroll
            for (int mi = 0; mi < 4; mi++) {
                LDSM_X4(ah[mi], Ah + a_off[mi] + koff);
                LDSM_X4(al[mi], Al + a_off[mi] + koff);
            }
            #pragma unroll
            for (int nip = 0; nip < 2; nip++) {
                LDSM_X4(bh[nip], Wh + b_off[nip] + koff);
                LDSM_X4(bl[nip], Wl + b_off[nip] + koff);
            }
            #pragma unroll
            for (int mi = 0; mi < 4; mi++) {
                #pragma unroll
                for (int ni = 0; ni < 4; ni++) {
                    int nip = ni >> 1, hf = (ni & 1) * 2;
                    MMA16816(acc[mi][ni], ah[mi], bh[nip][hf], bh[nip][hf + 1]);
                    MMA16816(acc[mi][ni], ah[mi], bl[nip][hf], bl[nip][hf + 1]);
                    MMA16816(acc[mi][ni], al[mi], bh[nip][hf], bh[nip][hf + 1]);
                }
            }
        }
    }
}

// fused QKV: grid (24, 32). blockIdx.x>>3 selects {q,k,v}.
__global__ void __launch_bounds__(256, 1)
gemm_qkv(const __nv_bfloat16* __restrict__ Ahi, const __nv_bfloat16* __restrict__ Alo,
         const float* __restrict__ q_b, const float* __restrict__ k_b,
         const float* __restrict__ v_b) {
    extern __shared__ char smraw[];
    uint32_t sb = smem_u32(smraw);
    int tid = threadIdx.x, wid = tid >> 5, lane = tid & 31;
    int w = blockIdx.x >> 3;
    int n0 = (blockIdx.x & 7) * 128, m0 = blockIdx.y * 128;

    const size_t NW = (size_t)En * En;
    const __nv_bfloat16* Whi = &g_whi[0][0] + (size_t)w * NW;
    const __nv_bfloat16* Wlo = &g_wlo[0][0] + (size_t)w * NW;
    const float* bias = (w == 0) ? q_b : (w == 1) ? k_b : v_b;
    __nv_bfloat16* ohi = (w == 0) ? g_qhi : (w == 1) ? g_khi : g_vhi;
    __nv_bfloat16* olo = (w == 0) ? g_qlo : (w == 1) ? g_klo : g_vlo;
    float scale = (w == 0) ? 0.125f * LOG2E : 1.0f;   // fold log2(e) into Q

    float acc[4][4][4];
    #pragma unroll
    for (int i = 0; i < 4; i++)
        #pragma unroll
        for (int j = 0; j < 4; j++)
            #pragma unroll
            for (int q = 0; q < 4; q++) acc[i][j][q] = 0.f;

    gemm_mainloop(sb, Ahi, Alo, Whi, Wlo, m0, n0, tid, wid, lane, acc);

    int rbase = m0 + (wid & 1) * 64 + (lane >> 2);
    int cbase = n0 + (wid >> 1) * 32 + (lane & 3) * 2;
    #pragma unroll
    for (int mi = 0; mi < 4; mi++) {
        #pragma unroll
        for (int ni = 0; ni < 4; ni++) {
            int c = cbase + ni * 8;
            float b0 = bias[c], b1 = bias[c + 1];
            #pragma unroll
            for (int half = 0; half < 2; half++) {
                int r = rbase + mi * 16 + half * 8;
                float v0 = (acc[mi][ni][half * 2 + 0] + b0) * scale;
                float v1 = (acc[mi][ni][half * 2 + 1] + b1) * scale;
                int t = r >> 2, b = r & 3;
                int h = c >> 6, d = c & 63;
                size_t ad = ((size_t)(b * Hn + h) * Tn + t) * DHn + d;
                __nv_bfloat16 h0 = __float2bfloat16(v0);
                __nv_bfloat16 h1 = __float2bfloat16(v1);
                *(__nv_bfloat162*)(ohi + ad) = __nv_bfloat162(h0, h1);
                *(__nv_bfloat162*)(olo + ad) = __nv_bfloat162(
                    __float2bfloat16(v0 - __bfloat162float(h0)),
                    __float2bfloat16(v1 - __bfloat162float(h1)));
            }
        }
    }
}

// out projection: fp32 row-major output
__global__ void __launch_bounds__(256, 1)
gemm_out(const __nv_bfloat16* __restrict__ Ahi, const __nv_bfloat16* __restrict__ Alo,
         const __nv_bfloat16* __restrict__ Whi, const __nv_bfloat16* __restrict__ Wlo,
         const float* __restrict__ bias, float* __restrict__ outf) {
    extern __shared__ char smraw[];
    uint32_t sb = smem_u32(smraw);
    int tid = threadIdx.x, wid = tid >> 5, lane = tid & 31;
    int n0 = blockIdx.x * 128, m0 = blockIdx.y * 128;

    float acc[4][4][4];
    #pragma unroll
    for (int i = 0; i < 4; i++)
        #pragma unroll
        for (int j = 0; j < 4; j++)
            #pragma unroll
            for (int q = 0; q < 4; q++) acc[i][j][q] = 0.f;

    gemm_mainloop(sb, Ahi, Alo, Whi, Wlo, m0, n0, tid, wid, lane, acc);

    int rbase = m0 + (wid & 1) * 64 + (lane >> 2);
    int cbase = n0 + (wid >> 1) * 32 + (lane & 3) * 2;
    #pragma unroll
    for (int mi = 0; mi < 4; mi++) {
        #pragma unroll
        for (int ni = 0; ni < 4; ni++) {
            int c = cbase + ni * 8;
            float b0 = bias[c], b1 = bias[c + 1];
            #pragma unroll
            for (int half = 0; half < 2; half++) {
                int r = rbase + mi * 16 + half * 8;
                float2 v;
                v.x = acc[mi][ni][half * 2 + 0] + b0;
                v.y = acc[mi][ni][half * 2 + 1] + b1;
                *(float2*)(outf + (size_t)r * 1024 + c) = v;
            }
        }
    }
}

// ================= fused prep: split query / split weights / posb / gate =================
// blocks [0,4096): split query; [4096,8192): split weights;
// [8192,8200): posb; [8200,16392): gate (8 warps per block).
#define PREP_BLOCKS 16392

__device__ __forceinline__ void split4(const float* src, __nv_bfloat16* hi,
                                       __nv_bfloat16* lo, size_t i) {
    float4 v = *(const float4*)(src + i);
    __nv_bfloat16 h0 = __float2bfloat16(v.x), h1 = __float2bfloat16(v.y);
    __nv_bfloat16 h2 = __float2bfloat16(v.z), h3 = __float2bfloat16(v.w);
    __nv_bfloat162* hp = (__nv_bfloat162*)(hi + i);
    __nv_bfloat162* lp = (__nv_bfloat162*)(lo + i);
    hp[0] = __nv_bfloat162(h0, h1); hp[1] = __nv_bfloat162(h2, h3);
    lp[0] = __nv_bfloat162(__float2bfloat16(v.x - __bfloat162float(h0)),
                           __float2bfloat16(v.y - __bfloat162float(h1)));
    lp[1] = __nv_bfloat162(__float2bfloat16(v.z - __bfloat162float(h2)),
                           __float2bfloat16(v.w - __bfloat162float(h3)));
}

__global__ void prep_kernel(const float* __restrict__ query,
                            const float* __restrict__ q_w, const float* __restrict__ k_w,
                            const float* __restrict__ v_w, const float* __restrict__ out_w,
                            const float* __restrict__ rel_bias,
                            const float* __restrict__ grep_w,
                            const float* __restrict__ grep_b,
                            const float* __restrict__ grep_a) {
    int bx = blockIdx.x, tid = threadIdx.x;
    if (bx < 4096) {
        // split query -> g_xhi/g_xlo
        size_t i = ((size_t)bx * 256 + tid) * 4;
        split4(query, g_xhi, g_xlo, i);
    } else if (bx < 8192) {
        const int NW = En * En;
        size_t i = ((size_t)(bx - 4096) * 256 + tid) * 4;
        int w = (int)(i / NW);
        size_t off = i - (size_t)w * NW;
        const float* src = (w == 0) ? q_w : (w == 1) ? k_w : (w == 2) ? v_w : out_w;
        float4 v = *(const float4*)(src + off);
        __nv_bfloat16 h0 = __float2bfloat16(v.x), h1 = __float2bfloat16(v.y);
        __nv_bfloat16 h2 = __float2bfloat16(v.z), h3 = __float2bfloat16(v.w);
        size_t gi = (size_t)w * NW + off;
        __nv_bfloat162* hp = (__nv_bfloat162*)(&g_whi[0][0] + gi);
        __nv_bfloat162* lp = (__nv_bfloat162*)(&g_wlo[0][0] + gi);
        hp[0] = __nv_bfloat162(h0, h1); hp[1] = __nv_bfloat162(h2, h3);
        lp[0] = __nv_bfloat162(__float2bfloat16(v.x - __bfloat162float(h0)),
                               __float2bfloat16(v.y - __bfloat162float(h1)));
        lp[1] = __nv_bfloat162(__float2bfloat16(v.z - __bfloat162float(h2)),
                               __float2bfloat16(v.w - __bfloat162float(h3)));
    } else if (bx < 8200) {
        int idx = (bx - 8192) * 256 + tid;
        if (idx >= RSPAN) return;
        int rp = idx - (Tn - 1);
        const int n = 16, max_exact = 8;
        int bucket = (rp > 0) ? n : 0;
        int arp = abs(rp);
        int add;
        if (arp < max_exact) add = arp;
        else {
            float v = (log2f((float)arp) - 3.0f) * 2.0f;
            add = max_exact + (int)v;
            if (add > n - 1) add = n - 1;
        }
        bucket += add;
        #pragma unroll
        for (int h = 0; h < Hn; h++)
            g_posb[h*RSPAN + idx] = rel_bias[bucket*Hn + h];
    } else {
        int warp = (bx - 8200) * 8 + (tid >> 5);
        int lane = tid & 31;
        int t = warp % Tn;
        int h = (warp / Tn) % Hn;
        int b = warp / (Tn * Hn);
        const float* q = query + ((size_t)t*Bn + b)*En + h*DHn;
        float q0 = q[lane], q1 = q[lane + 32];
        float s0 = 0.f, s1 = 0.f;
        #pragma unroll
        for (int e = 0; e < 8; e++) {
            float p = q0 * grep_w[e*DHn + lane] + q1 * grep_w[e*DHn + lane + 32];
            #pragma unroll
            for (int o = 16; o; o >>= 1) p += __shfl_xor_sync(0xffffffffu, p, o);
            p += grep_b[e];
            if (e < 4) s0 += p; else s1 += p;
        }
        if (lane == 0) {
            float ga = 1.f / (1.f + __expf(-s0));
            float gb = 1.f / (1.f + __expf(-s1));
            g_gate[warp] = (ga * (gb * grep_a[h] - 1.0f) + 2.0f) * LOG2E;  // fold log2(e)
        }
    }
}

// ================= HMMA flash attention (3-stage + separate Q region) =================
#define ATSZ  (64*72*2)          // 9216 B per 64x64 bf16 tile (stride 144B)
#define ABUF  (4*ATSZ)           // khi,klo,vhi,vlo = 36864 B per stage
#define ASM_Q  (3*ABUF)          // 110592 : Q hi (18432) + Q lo (18432)
#define ASM_LS (ASM_Q + 36864)   // 147456 : Ls[3][192] floats
#define ASM_GS (ASM_LS + 3*192*4)
#define ASM_TOTAL (ASM_GS + 512)
#define NTILE 16

__device__ __forceinline__ void attn_load_kv(uint32_t bbase,
        const __nv_bfloat16* kh, const __nv_bfloat16* kl,
        const __nv_bfloat16* vh, const __nv_bfloat16* vl, int s0, int tid) {
    #pragma unroll
    for (int it = 0; it < 2; it++) {
        int idx = tid + it * 256;
        int row = idx >> 3, seg = idx & 7;
        uint32_t doff = (uint32_t)row * 144 + seg * 16;
        size_t goff = (size_t)(s0 + row) * 64 + seg * 8;
        cpa16(bbase + 0*ATSZ + doff, kh + goff);
        cpa16(bbase + 1*ATSZ + doff, kl + goff);
        cpa16(bbase + 2*ATSZ + doff, vh + goff);
        cpa16(bbase + 3*ATSZ + doff, vl + goff);
    }
    CP_COMMIT();
}

__global__ void __launch_bounds__(256, 1) attn_mma() {
    extern __shared__ char smraw[];
    uint32_t sb = smem_u32(smraw);
    float* Lsf = (float*)(smraw + ASM_LS);
    float* gsf = (float*)(smraw + ASM_GS);
    const int tid = threadIdx.x, wid = tid >> 5, lane = tid & 31;
    const int t0 = blockIdx.x * 128;
    const int h = blockIdx.y, b = blockIdx.z;
    const size_t hoff = (size_t)(b*Hn + h) * Tn * DHn;
    const __nv_bfloat16 *qhg = g_qhi + hoff, *qlg = g_qlo + hoff;
    const __nv_bfloat16 *khg = g_khi + hoff, *klg = g_klo + hoff;
    const __nv_bfloat16 *vhg = g_vhi + hoff, *vlg = g_vlo + hoff;

    // ---- overlap: KV stages 0,1 + Q all in flight together ----
    attn_load_kv(sb + 0*ABUF, khg, klg, vhg, vlg, 0, tid);
    attn_load_kv(sb + 1*ABUF, khg, klg, vhg, vlg, 64, tid);
    #pragma unroll
    for (int it = 0; it < 4; it++) {
        int idx = tid + it * 256;
        int row = idx >> 3, seg = idx & 7;
        uint32_t doff = (uint32_t)row * 144 + seg * 16;
        size_t goff = (size_t)(t0 + row) * 64 + seg * 8;
        cpa16(sb + ASM_Q + doff, qhg + goff);
        cpa16(sb + ASM_Q + 18432 + doff, qlg + goff);
    }
    CP_COMMIT();
    if (tid < 191) {
        Lsf[tid]       = g_posb[h*RSPAN + 1023 + (0  - t0) + tid - 127];
        Lsf[192 + tid] = g_posb[h*RSPAN + 1023 + (64 - t0) + tid - 127];
    }
    if (tid < 128) gsf[tid] = g_gate[(b*Hn + h)*Tn + t0 + tid];
    CP_WAIT(0); __syncthreads();

    uint32_t qfh[4][4], qfl[4][4];
    {
        int arow = wid * 16 + (lane & 15);
        #pragma unroll
        for (int kt = 0; kt < 4; kt++) {
            uint32_t aoff = (uint32_t)arow * 144 + ((uint32_t)kt * 16 + (lane >> 4) * 8) * 2;
            LDSM_X4(qfh[kt], sb + ASM_Q + aoff);
            LDSM_X4(qfl[kt], sb + ASM_Q + 18432 + aoff);
        }
    }

    float O[8][4];
    #pragma unroll
    for (int j = 0; j < 8; j++) { O[j][0]=0.f; O[j][1]=0.f; O[j][2]=0.f; O[j][3]=0.f; }
    float m0r = -1e30f, m1r = -1e30f, l0r = 0.f, l1r = 0.f;

    const int r0l = wid * 16 + (lane >> 2);
    const int cb  = (lane & 3) * 2;
    const float g0 = gsf[r0l], g1 = gsf[r0l + 8];
    const int ib0 = 127 - r0l + cb;
    const int ib1 = ib0 - 8;

    int stage = 0, nstage = 2;
    #pragma unroll 1
    for (int st = 0; st < NTILE; st++) {
        if (st < NTILE - 1) CP_WAIT(1); else CP_WAIT(0);
        __syncthreads();
        if (st + 2 < NTILE) {
            int s0n = (st + 2) * 64;
            attn_load_kv(sb + nstage * ABUF, khg, klg, vhg, vlg, s0n, tid);
            if (tid < 191)
                Lsf[nstage * 192 + tid] = g_posb[h*RSPAN + 1023 + (s0n - t0) + tid - 127];
            nstage = (nstage == 2) ? 0 : nstage + 1;
        }
        uint32_t bb = sb + stage * ABUF;
        float* Lss = Lsf + stage * 192;
        stage = (stage == 2) ? 0 : stage + 1;

        // ---- S init = gate * posb (bias), then S += Q K^T ----
        float S[8][4];
        #pragma unroll
        for (int j = 0; j < 8; j++) {
            S[j][0] = g0 * Lss[ib0 + 8*j];
            S[j][1] = g0 * Lss[ib0 + 8*j + 1];
            S[j][2] = g1 * Lss[ib1 + 8*j];
            S[j][3] = g1 * Lss[ib1 + 8*j + 1];
        }
        #pragma unroll
        for (int kt = 0; kt < 4; kt++) {
            #pragma unroll
            for (int nip = 0; nip < 4; nip++) {
                uint32_t boff = ((uint32_t)(nip*16 + ((lane>>4)&1)*8 + (lane&7))) * 144
                              + ((uint32_t)(kt*16 + ((lane>>3)&1)*8)) * 2;
                uint32_t bh[4], bl[4];
                LDSM_X4(bh, bb + boff);
                LDSM_X4(bl, bb + ATSZ + boff);
                #pragma unroll
                for (int hf = 0; hf < 2; hf++) {
                    int j = nip*2 + hf;
                    MMA16816(S[j], qfh[kt], bh[hf*2], bh[hf*2+1]);
                    MMA16816(S[j], qfh[kt], bl[hf*2], bl[hf*2+1]);
                    MMA16816(S[j], qfl[kt], bh[hf*2], bh[hf*2+1]);
                }
            }
        }

        // ---- online softmax in base-2 domain ----
        {
            float tm = fmaxf(S[0][0], S[0][1]);
            #pragma unroll
            for (int j = 1; j < 8; j++) tm = fmaxf(tm, fmaxf(S[j][0], S[j][1]));
            tm = fmaxf(tm, __shfl_xor_sync(0xffffffffu, tm, 1));
            tm = fmaxf(tm, __shfl_xor_sync(0xffffffffu, tm, 2));
            float mn = fmaxf(m0r, tm);
            float corr = exp2f(m0r - mn);
            m0r = mn;
            float rs = 0.f;
            #pragma unroll
            for (int j = 0; j < 8; j++) {
                S[j][0] = exp2f(S[j][0] - mn);
                S[j][1] = exp2f(S[j][1] - mn);
                rs += S[j][0] + S[j][1];
            }
            rs += __shfl_xor_sync(0xffffffffu, rs, 1);
            rs += __shfl_xor_sync(0xffffffffu, rs, 2);
            l0r = l0r * corr + rs;
            #pragma unroll
            for (int j = 0; j < 8; j++) { O[j][0] *= corr; O[j][1] *= corr; }
        }
        {
            float tm = fmaxf(S[0][2], S[0][3]);
            #pragma unroll
            for (int j = 1; j < 8; j++) tm = fmaxf(tm, fmaxf(S[j][2], S[j][3]));
            tm = fmaxf(tm, __shfl_xor_sync(0xffffffffu, tm, 1));
            tm = fmaxf(tm, __shfl_xor_sync(0xffffffffu, tm, 2));
            float mn = fmaxf(m1r, tm);
            float corr = exp2f(m1r - mn);
            m1r = mn;
            float rs = 0.f;
            #pragma unroll
            for (int j = 0; j < 8; j++) {
                S[j][2] = exp2f(S[j][2] - mn);
                S[j][3] = exp2f(S[j][3] - mn);
                rs += S[j][2] + S[j][3];
            }
            rs += __shfl_xor_sync(0xffffffffu, rs, 1);
            rs += __shfl_xor_sync(0xffffffffu, rs, 2);
            l1r = l1r * corr + rs;
            #pragma unroll
            for (int j = 0; j < 8; j++) { O[j][2] *= corr; O[j][3] *= corr; }
        }

        // ---- O += P V ----
        #pragma unroll
        for (int kt = 0; kt < 4; kt++) {
            uint32_t ph[4], pl[4];
            {
                float p00 = S[2*kt][0],   p01 = S[2*kt][1];
                float p02 = S[2*kt][2],   p03 = S[2*kt][3];
                float p10 = S[2*kt+1][0], p11 = S[2*kt+1][1];
                float p12 = S[2*kt+1][2], p13 = S[2*kt+1][3];
                ph[0] = pack_bf16x2(p00, p01);
                ph[1] = pack_bf16x2(p02, p03);
                ph[2] = pack_bf16x2(p10, p11);
                ph[3] = pack_bf16x2(p12, p13);
                pl[0] = pack_bf16x2(p00 - bf16_rt(p00), p01 - bf16_rt(p01));
                pl[1] = pack_bf16x2(p02 - bf16_rt(p02), p03 - bf16_rt(p03));
                pl[2] = pack_bf16x2(p10 - bf16_rt(p10), p11 - bf16_rt(p11));
                pl[3] = pack_bf16x2(p12 - bf16_rt(p12), p13 - bf16_rt(p13));
            }
            #pragma unroll
            for (int g = 0; g < 4; g++) {
                uint32_t voff = ((uint32_t)(kt*16 + (lane & 15))) * 144
                              + ((uint32_t)(g*16 + (lane >> 4) * 8)) * 2;
                uint32_t vh[4], vl[4];
                LDSM_X4_T(vh, bb + 2*ATSZ + voff);
                LDSM_X4_T(vl, bb + 3*ATSZ + voff);
                MMA16816(O[2*g],   ph, vh[0], vh[1]);
                MMA16816(O[2*g],   pl, vh[0], vh[1]);
                MMA16816(O[2*g],   ph, vl[0], vl[1]);
                MMA16816(O[2*g+1], ph, vh[2], vh[3]);
                MMA16816(O[2*g+1], pl, vh[2], vh[3]);
                MMA16816(O[2*g+1], ph, vl[2], vl[3]);
            }
        }
    }

    // ---- epilogue ----
    float inv0 = 1.f / l0r, inv1 = 1.f / l1r;
    int tg0 = t0 + r0l;
    #pragma unroll
    for (int j = 0; j < 8; j++) {
        int d = h * 64 + 8*j + cb;
        {
            float v0 = O[j][0] * inv0, v1 = O[j][1] * inv0;
            __nv_bfloat16 h0 = __float2bfloat16(v0), h1 = __float2bfloat16(v1);
            size_t ad = ((size_t)tg0 * Bn + b) * En + d;
            *(__nv_bfloat162*)(g_xhi + ad) = __nv_bfloat162(h0, h1);
            *(__nv_bfloat162*)(g_xlo + ad) = __nv_bfloat162(
                __float2bfloat16(v0 - __bfloat162float(h0)),
                __float2bfloat16(v1 - __bfloat162float(h1)));
        }
        {
            float v0 = O[j][2] * inv1, v1 = O[j][3] * inv1;
            __nv_bfloat16 h0 = __float2bfloat16(v0), h1 = __float2bfloat16(v1);
            size_t ad = ((size_t)(tg0 + 8) * Bn + b) * En + d;
            *(__nv_bfloat162*)(g_xhi + ad) = __nv_bfloat162(h0, h1);
            *(__nv_bfloat162*)(g_xlo + ad) = __nv_bfloat162(
                __float2bfloat16(v0 - __bfloat162float(h0)),
                __float2bfloat16(v1 - __bfloat162float(h1)));
        }
    }
}

// ---------------- launch ----------------
extern "C" void kernel_launch(void* const* d_in, const int* in_sizes, int n_in,
                              void* d_out, int out_size) {
    const float* query  = (const float*)d_in[0];
    const float* q_w    = (const float*)d_in[1];
    const float* q_b    = (const float*)d_in[2];
    const float* k_w    = (const float*)d_in[3];
    const float* k_b    = (const float*)d_in[4];
    const float* v_w    = (const float*)d_in[5];
    const float* v_b    = (const float*)d_in[6];
    const float* out_w  = (const float*)d_in[7];
    const float* out_b  = (const float*)d_in[8];
    const float* rel_bias = (const float*)d_in[9];
    const float* grep_w = (const float*)d_in[10];
    const float* grep_b = (const float*)d_in[11];
    const float* grep_a = (const float*)d_in[12];
    float* out = (float*)d_out;

    __nv_bfloat16 *p_xhi, *p_xlo, *p_whi, *p_wlo;
    cudaGetSymbolAddress((void**)&p_xhi, g_xhi);
    cudaGetSymbolAddress((void**)&p_xlo, g_xlo);
    cudaGetSymbolAddress((void**)&p_whi, g_whi);
    cudaGetSymbolAddress((void**)&p_wlo, g_wlo);

    cudaFuncSetAttribute(gemm_qkv, cudaFuncAttributeMaxDynamicSharedMemorySize, SMEM_G);
    cudaFuncSetAttribute(gemm_out, cudaFuncAttributeMaxDynamicSharedMemorySize, SMEM_G);
    cudaFuncSetAttribute(attn_mma, cudaFuncAttributeMaxDynamicSharedMemorySize, ASM_TOTAL);

    prep_kernel<<<PREP_BLOCKS, 256>>>(query, q_w, k_w, v_w, out_w,
                                      rel_bias, grep_w, grep_b, grep_a);

    dim3 gq(24, (Tn*Bn)/128);
    gemm_qkv<<<gq, 256, SMEM_G>>>(p_xhi, p_xlo, q_b, k_b, v_b);

    dim3 ga(Tn/128, Hn, Bn);
    attn_mma<<<ga, 256, ASM_TOTAL>>>();

    const int NW = En*En;
    dim3 gg(En/128, (Tn*Bn)/128);
    gemm_out<<<gg, 256, SMEM_G>>>(p_xhi, p_xlo, p_whi + 3*(size_t)NW, p_wlo + 3*(size_t)NW,
                                  out_b, out);

    (void)in_sizes; (void)n_in; (void)out_size;
}

// round 7
// speedup vs baseline: 3.4649x; 1.1257x over previous
#include <cuda_runtime.h>
#include <cuda_bf16.h>
#include <math.h>
#include <cstdint>

#define Tn 1024
#define Bn 4
#define En 1024
#define Hn 16
#define DHn 64
#define RSPAN (2*Tn - 1)   // 2047
#define LOG2E 1.4426950408889634f

// ---------------- scratch ----------------
__device__ float g_gate[Bn*Hn*Tn];
__device__ float g_posb[Hn*RSPAN];

__device__ __nv_bfloat16 g_xhi[(size_t)Tn*Bn*En];
__device__ __nv_bfloat16 g_xlo[(size_t)Tn*Bn*En];
__device__ __nv_bfloat16 g_whi[4][(size_t)En*En];
__device__ __nv_bfloat16 g_wlo[4][(size_t)En*En];

__device__ __nv_bfloat16 g_qhi[(size_t)Bn*Hn*Tn*DHn];
__device__ __nv_bfloat16 g_qlo[(size_t)Bn*Hn*Tn*DHn];
__device__ __nv_bfloat16 g_khi[(size_t)Bn*Hn*Tn*DHn];
__device__ __nv_bfloat16 g_klo[(size_t)Bn*Hn*Tn*DHn];
__device__ __nv_bfloat16 g_vhi[(size_t)Bn*Hn*Tn*DHn];
__device__ __nv_bfloat16 g_vlo[(size_t)Bn*Hn*Tn*DHn];

// ================= helpers =================
__device__ __forceinline__ uint32_t smem_u32(const void* p) {
    uint32_t a;
    asm("{ .reg .u64 t; cvta.to.shared.u64 t, %1; cvt.u32.u64 %0, t; }" : "=r"(a) : "l"(p));
    return a;
}
__device__ __forceinline__ void cpa16(uint32_t dst, const void* src) {
    asm volatile("cp.async.cg.shared.global [%0], [%1], 16;" :: "r"(dst), "l"(src));
}
#define CP_COMMIT() asm volatile("cp.async.commit_group;" ::: "memory")
#define CP_WAIT(n)  asm volatile("cp.async.wait_group %0;" :: "n"(n) : "memory")

#define LDSM_X4(r, a) \
    asm volatile("ldmatrix.sync.aligned.m8n8.x4.shared.b16 {%0,%1,%2,%3}, [%4];" \
        : "=r"((r)[0]), "=r"((r)[1]), "=r"((r)[2]), "=r"((r)[3]) : "r"(a))
#define LDSM_X4_T(r, a) \
    asm volatile("ldmatrix.sync.aligned.m8n8.x4.trans.shared.b16 {%0,%1,%2,%3}, [%4];" \
        : "=r"((r)[0]), "=r"((r)[1]), "=r"((r)[2]), "=r"((r)[3]) : "r"(a))

#define MMA16816(c, a, b0, b1) \
    asm volatile("mma.sync.aligned.m16n8k16.row.col.f32.bf16.bf16.f32 " \
        "{%0,%1,%2,%3}, {%4,%5,%6,%7}, {%8,%9}, {%0,%1,%2,%3};" \
        : "+f"((c)[0]), "+f"((c)[1]), "+f"((c)[2]), "+f"((c)[3]) \
        : "r"((a)[0]), "r"((a)[1]), "r"((a)[2]), "r"((a)[3]), "r"(b0), "r"(b1))

__device__ __forceinline__ uint32_t pack_bf16x2(float lo, float hi) {
    uint32_t r;
    asm("cvt.rn.bf16x2.f32 %0, %1, %2;" : "=r"(r) : "f"(hi), "f"(lo));
    return r;
}
__device__ __forceinline__ float bf16_rt(float x) {
    return __bfloat162float(__float2bfloat16(x));
}

// ================= HMMA bf16-split GEMM (2-stage, 2 CTAs/SM) =================
#define ST 40
#define TILE_H (128*ST)
#define BUF_B  (4*TILE_H*2)      // 40960 bytes per stage
#define SMEM_G (2*BUF_B)         // 81920
#define NCH 32

__device__ __forceinline__ void load_tile_mma(uint32_t sdst, const __nv_bfloat16* g,
                                              int r0, int kc, int tid) {
    #pragma unroll
    for (int it = 0; it < 2; it++) {
        int idx = tid + it * 256;
        int row = idx >> 2, seg = idx & 3;
        uint32_t dst = sdst + (uint32_t)(row * ST) * 2u + seg * 16;
        const char* src = (const char*)(g + (size_t)(r0 + row) * 1024 + kc * 32 + seg * 8);
        cpa16(dst, src);
    }
}
__device__ __forceinline__ void load_stage(uint32_t bb,
        const __nv_bfloat16* Ahi, const __nv_bfloat16* Alo,
        const __nv_bfloat16* Whi, const __nv_bfloat16* Wlo,
        int m0, int n0, int kc, int tid) {
    load_tile_mma(bb + 0 * TILE_H * 2, Ahi, m0, kc, tid);
    load_tile_mma(bb + 1 * TILE_H * 2, Alo, m0, kc, tid);
    load_tile_mma(bb + 2 * TILE_H * 2, Whi, n0, kc, tid);
    load_tile_mma(bb + 3 * TILE_H * 2, Wlo, n0, kc, tid);
    CP_COMMIT();
}

__device__ __forceinline__ void gemm_mainloop(uint32_t sb,
        const __nv_bfloat16* Ahi, const __nv_bfloat16* Alo,
        const __nv_bfloat16* Whi, const __nv_bfloat16* Wlo,
        int m0, int n0, int tid, int wid, int lane, float acc[4][4][4]) {
    int warp_m = wid & 1;
    int warp_n = wid >> 1;
    uint32_t a_off[4];
    #pragma unroll
    for (int mi = 0; mi < 4; mi++) {
        int arow = warp_m * 64 + mi * 16 + (lane & 15);
        a_off[mi] = (uint32_t)(arow * ST + (lane >> 4) * 8) * 2u;
    }
    uint32_t b_off[2];
    #pragma unroll
    for (int nip = 0; nip < 2; nip++) {
        int nrow = warp_n * 32 + nip * 16 + ((lane >> 4) & 1) * 8 + (lane & 7);
        b_off[nip] = (uint32_t)(nrow * ST + ((lane >> 3) & 1) * 8) * 2u;
    }

    load_stage(sb, Ahi, Alo, Whi, Wlo, m0, n0, 0, tid);

    #pragma unroll 1
    for (int kc = 0; kc < NCH; kc++) {
        CP_WAIT(0);
        __syncthreads();
        if (kc + 1 < NCH)
            load_stage(sb + ((kc + 1) & 1) * BUF_B, Ahi, Alo, Whi, Wlo, m0, n0, kc + 1, tid);
        uint32_t bb = sb + (kc & 1) * BUF_B;
        uint32_t Ah = bb, Al = bb + TILE_H * 2, Wh = bb + 2 * TILE_H * 2, Wl = bb + 3 * TILE_H * 2;
        #pragma unroll
        for (int ks = 0; ks < 2; ks++) {
            uint32_t koff = ks * 32;
            uint32_t bh[2][4], bl[2][4];
            #pragma unroll
            for (int nip = 0; nip < 2; nip++) {
                LDSM_X4(bh[nip], Wh + b_off[nip] + koff);
                LDSM_X4(bl[nip], Wl + b_off[nip] + koff);
            }
            #pragma unroll
            for (int mi = 0; mi < 4; mi++) {
                uint32_t ah[4], al[4];
                LDSM_X4(ah, Ah + a_off[mi] + koff);
                LDSM_X4(al, Al + a_off[mi] + koff);
                #pragma unroll
                for (int ni = 0; ni < 4; ni++) {
                    int nip = ni >> 1, hf = (ni & 1) * 2;
                    MMA16816(acc[mi][ni], ah, bh[nip][hf], bh[nip][hf + 1]);
                    MMA16816(acc[mi][ni], ah, bl[nip][hf], bl[nip][hf + 1]);
                    MMA16816(acc[mi][ni], al, bh[nip][hf], bh[nip][hf + 1]);
                }
            }
        }
    }
}

// fused QKV: grid (24, 32)
__global__ void __launch_bounds__(256, 2)
gemm_qkv(const __nv_bfloat16* __restrict__ Ahi, const __nv_bfloat16* __restrict__ Alo,
         const float* __restrict__ q_b, const float* __restrict__ k_b,
         const float* __restrict__ v_b) {
    extern __shared__ char smraw[];
    uint32_t sb = smem_u32(smraw);
    int tid = threadIdx.x, wid = tid >> 5, lane = tid & 31;
    int w = blockIdx.x >> 3;
    int n0 = (blockIdx.x & 7) * 128, m0 = blockIdx.y * 128;

    const size_t NW = (size_t)En * En;
    const __nv_bfloat16* Whi = &g_whi[0][0] + (size_t)w * NW;
    const __nv_bfloat16* Wlo = &g_wlo[0][0] + (size_t)w * NW;
    const float* bias = (w == 0) ? q_b : (w == 1) ? k_b : v_b;
    __nv_bfloat16* ohi = (w == 0) ? g_qhi : (w == 1) ? g_khi : g_vhi;
    __nv_bfloat16* olo = (w == 0) ? g_qlo : (w == 1) ? g_klo : g_vlo;
    float scale = (w == 0) ? 0.125f * LOG2E : 1.0f;

    float acc[4][4][4];
    #pragma unroll
    for (int i = 0; i < 4; i++)
        #pragma unroll
        for (int j = 0; j < 4; j++)
            #pragma unroll
            for (int q = 0; q < 4; q++) acc[i][j][q] = 0.f;

    gemm_mainloop(sb, Ahi, Alo, Whi, Wlo, m0, n0, tid, wid, lane, acc);

    int rbase = m0 + (wid & 1) * 64 + (lane >> 2);
    int cbase = n0 + (wid >> 1) * 32 + (lane & 3) * 2;
    #pragma unroll
    for (int mi = 0; mi < 4; mi++) {
        #pragma unroll
        for (int ni = 0; ni < 4; ni++) {
            int c = cbase + ni * 8;
            float b0 = bias[c], b1 = bias[c + 1];
            #pragma unroll
            for (int half = 0; half < 2; half++) {
                int r = rbase + mi * 16 + half * 8;
                float v0 = (acc[mi][ni][half * 2 + 0] + b0) * scale;
                float v1 = (acc[mi][ni][half * 2 + 1] + b1) * scale;
                int t = r >> 2, b = r & 3;
                int h = c >> 6, d = c & 63;
                size_t ad = ((size_t)(b * Hn + h) * Tn + t) * DHn + d;
                __nv_bfloat16 h0 = __float2bfloat16(v0);
                __nv_bfloat16 h1 = __float2bfloat16(v1);
                *(__nv_bfloat162*)(ohi + ad) = __nv_bfloat162(h0, h1);
                *(__nv_bfloat162*)(olo + ad) = __nv_bfloat162(
                    __float2bfloat16(v0 - __bfloat162float(h0)),
                    __float2bfloat16(v1 - __bfloat162float(h1)));
            }
        }
    }
}

// out projection
__global__ void __launch_bounds__(256, 2)
gemm_out(const __nv_bfloat16* __restrict__ Ahi, const __nv_bfloat16* __restrict__ Alo,
         const __nv_bfloat16* __restrict__ Whi, const __nv_bfloat16* __restrict__ Wlo,
         const float* __restrict__ bias, float* __restrict__ outf) {
    extern __shared__ char smraw[];
    uint32_t sb = smem_u32(smraw);
    int tid = threadIdx.x, wid = tid >> 5, lane = tid & 31;
    int n0 = blockIdx.x * 128, m0 = blockIdx.y * 128;

    float acc[4][4][4];
    #pragma unroll
    for (int i = 0; i < 4; i++)
        #pragma unroll
        for (int j = 0; j < 4; j++)
            #pragma unroll
            for (int q = 0; q < 4; q++) acc[i][j][q] = 0.f;

    gemm_mainloop(sb, Ahi, Alo, Whi, Wlo, m0, n0, tid, wid, lane, acc);

    int rbase = m0 + (wid & 1) * 64 + (lane >> 2);
    int cbase = n0 + (wid >> 1) * 32 + (lane & 3) * 2;
    #pragma unroll
    for (int mi = 0; mi < 4; mi++) {
        #pragma unroll
        for (int ni = 0; ni < 4; ni++) {
            int c = cbase + ni * 8;
            float b0 = bias[c], b1 = bias[c + 1];
            #pragma unroll
            for (int half = 0; half < 2; half++) {
                int r = rbase + mi * 16 + half * 8;
                float2 v;
                v.x = acc[mi][ni][half * 2 + 0] + b0;
                v.y = acc[mi][ni][half * 2 + 1] + b1;
                *(float2*)(outf + (size_t)r * 1024 + c) = v;
            }
        }
    }
}

// ================= fused prep =================
#define PREP_BLOCKS 16392

__device__ __forceinline__ void split4(const float* src, __nv_bfloat16* hi,
                                       __nv_bfloat16* lo, size_t i) {
    float4 v = *(const float4*)(src + i);
    __nv_bfloat16 h0 = __float2bfloat16(v.x), h1 = __float2bfloat16(v.y);
    __nv_bfloat16 h2 = __float2bfloat16(v.z), h3 = __float2bfloat16(v.w);
    __nv_bfloat162* hp = (__nv_bfloat162*)(hi + i);
    __nv_bfloat162* lp = (__nv_bfloat162*)(lo + i);
    hp[0] = __nv_bfloat162(h0, h1); hp[1] = __nv_bfloat162(h2, h3);
    lp[0] = __nv_bfloat162(__float2bfloat16(v.x - __bfloat162float(h0)),
                           __float2bfloat16(v.y - __bfloat162float(h1)));
    lp[1] = __nv_bfloat162(__float2bfloat16(v.z - __bfloat162float(h2)),
                           __float2bfloat16(v.w - __bfloat162float(h3)));
}

__global__ void prep_kernel(const float* __restrict__ query,
                            const float* __restrict__ q_w, const float* __restrict__ k_w,
                            const float* __restrict__ v_w, const float* __restrict__ out_w,
                            const float* __restrict__ rel_bias,
                            const float* __restrict__ grep_w,
                            const float* __restrict__ grep_b,
                            const float* __restrict__ grep_a) {
    int bx = blockIdx.x, tid = threadIdx.x;
    if (bx < 4096) {
        size_t i = ((size_t)bx * 256 + tid) * 4;
        split4(query, g_xhi, g_xlo, i);
    } else if (bx < 8192) {
        const int NW = En * En;
        size_t i = ((size_t)(bx - 4096) * 256 + tid) * 4;
        int w = (int)(i / NW);
        size_t off = i - (size_t)w * NW;
        const float* src = (w == 0) ? q_w : (w == 1) ? k_w : (w == 2) ? v_w : out_w;
        float4 v = *(const float4*)(src + off);
        __nv_bfloat16 h0 = __float2bfloat16(v.x), h1 = __float2bfloat16(v.y);
        __nv_bfloat16 h2 = __float2bfloat16(v.z), h3 = __float2bfloat16(v.w);
        size_t gi = (size_t)w * NW + off;
        __nv_bfloat162* hp = (__nv_bfloat162*)(&g_whi[0][0] + gi);
        __nv_bfloat162* lp = (__nv_bfloat162*)(&g_wlo[0][0] + gi);
        hp[0] = __nv_bfloat162(h0, h1); hp[1] = __nv_bfloat162(h2, h3);
        lp[0] = __nv_bfloat162(__float2bfloat16(v.x - __bfloat162float(h0)),
                               __float2bfloat16(v.y - __bfloat162float(h1)));
        lp[1] = __nv_bfloat162(__float2bfloat16(v.z - __bfloat162float(h2)),
                               __float2bfloat16(v.w - __bfloat162float(h3)));
    } else if (bx < 8200) {
        int idx = (bx - 8192) * 256 + tid;
        if (idx >= RSPAN) return;
        int rp = idx - (Tn - 1);
        const int n = 16, max_exact = 8;
        int bucket = (rp > 0) ? n : 0;
        int arp = abs(rp);
        int add;
        if (arp < max_exact) add = arp;
        else {
            float v = (log2f((float)arp) - 3.0f) * 2.0f;
            add = max_exact + (int)v;
            if (add > n - 1) add = n - 1;
        }
        bucket += add;
        #pragma unroll
        for (int h = 0; h < Hn; h++)
            g_posb[h*RSPAN + idx] = rel_bias[bucket*Hn + h];
    } else {
        int warp = (bx - 8200) * 8 + (tid >> 5);
        int lane = tid & 31;
        int t = warp % Tn;
        int h = (warp / Tn) % Hn;
        int b = warp / (Tn * Hn);
        const float* q = query + ((size_t)t*Bn + b)*En + h*DHn;
        float q0 = q[lane], q1 = q[lane + 32];
        float s0 = 0.f, s1 = 0.f;
        #pragma unroll
        for (int e = 0; e < 8; e++) {
            float p = q0 * grep_w[e*DHn + lane] + q1 * grep_w[e*DHn + lane + 32];
            #pragma unroll
            for (int o = 16; o; o >>= 1) p += __shfl_xor_sync(0xffffffffu, p, o);
            p += grep_b[e];
            if (e < 4) s0 += p; else s1 += p;
        }
        if (lane == 0) {
            float ga = 1.f / (1.f + __expf(-s0));
            float gb = 1.f / (1.f + __expf(-s1));
            g_gate[warp] = (ga * (gb * grep_a[h] - 1.0f) + 2.0f) * LOG2E;
        }
    }
}

// ================= HMMA flash attention (4 warps, 64 q-rows, 2 CTAs/SM) =================
#define ATSZ  (64*72*2)            // 9216 B per 64x64 bf16 tile
#define ABUF  (4*ATSZ)             // 36864 B per KV stage
#define ASM_Q  (2*ABUF)            // 73728 : Qhi 9216 + Qlo 9216
#define ASM_LS (ASM_Q + 18432)     // 92160 : Ls[2][128] floats
#define ASM_GS (ASM_LS + 2*128*4)  // 93184 : gs 64 floats
#define ASM_TOTAL (ASM_GS + 320)   // 93504
#define NTILE 16

__device__ __forceinline__ void attn_load_kv(uint32_t bbase,
        const __nv_bfloat16* kh, const __nv_bfloat16* kl,
        const __nv_bfloat16* vh, const __nv_bfloat16* vl, int s0, int tid) {
    #pragma unroll
    for (int it = 0; it < 4; it++) {
        int idx = tid + it * 128;
        int row = idx >> 3, seg = idx & 7;
        uint32_t doff = (uint32_t)row * 144 + seg * 16;
        size_t goff = (size_t)(s0 + row) * 64 + seg * 8;
        cpa16(bbase + 0*ATSZ + doff, kh + goff);
        cpa16(bbase + 1*ATSZ + doff, kl + goff);
        cpa16(bbase + 2*ATSZ + doff, vh + goff);
        cpa16(bbase + 3*ATSZ + doff, vl + goff);
    }
    CP_COMMIT();
}

__global__ void __launch_bounds__(128, 2) attn_mma() {
    extern __shared__ char smraw[];
    uint32_t sb = smem_u32(smraw);
    float* Lsf = (float*)(smraw + ASM_LS);
    float* gsf = (float*)(smraw + ASM_GS);
    const int tid = threadIdx.x, wid = tid >> 5, lane = tid & 31;
    const int t0 = blockIdx.x * 64;
    const int h = blockIdx.y, b = blockIdx.z;
    const size_t hoff = (size_t)(b*Hn + h) * Tn * DHn;
    const __nv_bfloat16 *qhg = g_qhi + hoff, *qlg = g_qlo + hoff;
    const __nv_bfloat16 *khg = g_khi + hoff, *klg = g_klo + hoff;
    const __nv_bfloat16 *vhg = g_vhi + hoff, *vlg = g_vlo + hoff;

    // ---- prologue: KV(0) + Q in flight together ----
    attn_load_kv(sb, khg, klg, vhg, vlg, 0, tid);
    #pragma unroll
    for (int it = 0; it < 4; it++) {
        int idx = tid + it * 128;
        int row = idx >> 3, seg = idx & 7;
        uint32_t doff = (uint32_t)row * 144 + seg * 16;
        size_t goff = (size_t)(t0 + row) * 64 + seg * 8;
        cpa16(sb + ASM_Q + doff, qhg + goff);
        cpa16(sb + ASM_Q + 9216 + doff, qlg + goff);
    }
    CP_COMMIT();
    if (tid < 127)
        Lsf[tid] = g_posb[h*RSPAN + 1023 + (0 - t0) + tid - 63];
    if (tid < 64) gsf[tid] = g_gate[(b*Hn + h)*Tn + t0 + tid];
    CP_WAIT(0); __syncthreads();

    uint32_t qfh[4][4], qfl[4][4];
    {
        int arow = wid * 16 + (lane & 15);
        #pragma unroll
        for (int kt = 0; kt < 4; kt++) {
            uint32_t aoff = (uint32_t)arow * 144 + ((uint32_t)kt * 16 + (lane >> 4) * 8) * 2;
            LDSM_X4(qfh[kt], sb + ASM_Q + aoff);
            LDSM_X4(qfl[kt], sb + ASM_Q + 9216 + aoff);
        }
    }

    float O[8][4];
    #pragma unroll
    for (int j = 0; j < 8; j++) { O[j][0]=0.f; O[j][1]=0.f; O[j][2]=0.f; O[j][3]=0.f; }
    float m0r = -1e30f, m1r = -1e30f, l0r = 0.f, l1r = 0.f;

    const int r0l = wid * 16 + (lane >> 2);     // 0..63
    const int cb  = (lane & 3) * 2;
    const float g0 = gsf[r0l], g1 = gsf[r0l + 8];
    const int ib0 = 63 - r0l + cb;
    const int ib1 = ib0 - 8;

    #pragma unroll 1
    for (int st = 0; st < NTILE; st++) {
        if (st > 0) { CP_WAIT(0); __syncthreads(); }
        if (st + 1 < NTILE) {
            int s0n = (st + 1) * 64;
            attn_load_kv(sb + ((st + 1) & 1) * ABUF, khg, klg, vhg, vlg, s0n, tid);
            if (tid < 127)
                Lsf[((st + 1) & 1) * 128 + tid] =
                    g_posb[h*RSPAN + 1023 + (s0n - t0) + tid - 63];
        }
        uint32_t bb = sb + (st & 1) * ABUF;
        float* Lss = Lsf + (st & 1) * 128;

        // ---- S init = gate*posb; S += Q K^T ----
        float S[8][4];
        #pragma unroll
        for (int j = 0; j < 8; j++) {
            S[j][0] = g0 * Lss[ib0 + 8*j];
            S[j][1] = g0 * Lss[ib0 + 8*j + 1];
            S[j][2] = g1 * Lss[ib1 + 8*j];
            S[j][3] = g1 * Lss[ib1 + 8*j + 1];
        }
        #pragma unroll
        for (int kt = 0; kt < 4; kt++) {
            #pragma unroll
            for (int nip = 0; nip < 4; nip++) {
                uint32_t boff = ((uint32_t)(nip*16 + ((lane>>4)&1)*8 + (lane&7))) * 144
                              + ((uint32_t)(kt*16 + ((lane>>3)&1)*8)) * 2;
                uint32_t bh[4], bl[4];
                LDSM_X4(bh, bb + boff);
                LDSM_X4(bl, bb + ATSZ + boff);
                #pragma unroll
                for (int hf = 0; hf < 2; hf++) {
                    int j = nip*2 + hf;
                    MMA16816(S[j], qfh[kt], bh[hf*2], bh[hf*2+1]);
                    MMA16816(S[j], qfh[kt], bl[hf*2], bl[hf*2+1]);
                    MMA16816(S[j], qfl[kt], bh[hf*2], bh[hf*2+1]);
                }
            }
        }

        // ---- online softmax (base-2) ----
        {
            float tm = fmaxf(S[0][0], S[0][1]);
            #pragma unroll
            for (int j = 1; j < 8; j++) tm = fmaxf(tm, fmaxf(S[j][0], S[j][1]));
            tm = fmaxf(tm, __shfl_xor_sync(0xffffffffu, tm, 1));
            tm = fmaxf(tm, __shfl_xor_sync(0xffffffffu, tm, 2));
            float mn = fmaxf(m0r, tm);
            float corr = exp2f(m0r - mn);
            m0r = mn;
            float rs = 0.f;
            #pragma unroll
            for (int j = 0; j < 8; j++) {
                S[j][0] = exp2f(S[j][0] - mn);
                S[j][1] = exp2f(S[j][1] - mn);
                rs += S[j][0] + S[j][1];
            }
            rs += __shfl_xor_sync(0xffffffffu, rs, 1);
            rs += __shfl_xor_sync(0xffffffffu, rs, 2);
            l0r = l0r * corr + rs;
            #pragma unroll
            for (int j = 0; j < 8; j++) { O[j][0] *= corr; O[j][1] *= corr; }
        }
        {
            float tm = fmaxf(S[0][2], S[0][3]);
            #pragma unroll
            for (int j = 1; j < 8; j++) tm = fmaxf(tm, fmaxf(S[j][2], S[j][3]));
            tm = fmaxf(tm, __shfl_xor_sync(0xffffffffu, tm, 1));
            tm = fmaxf(tm, __shfl_xor_sync(0xffffffffu, tm, 2));
            float mn = fmaxf(m1r, tm);
            float corr = exp2f(m1r - mn);
            m1r = mn;
            float rs = 0.f;
            #pragma unroll
            for (int j = 0; j < 8; j++) {
                S[j][2] = exp2f(S[j][2] - mn);
                S[j][3] = exp2f(S[j][3] - mn);
                rs += S[j][2] + S[j][3];
            }
            rs += __shfl_xor_sync(0xffffffffu, rs, 1);
            rs += __shfl_xor_sync(0xffffffffu, rs, 2);
            l1r = l1r * corr + rs;
            #pragma unroll
            for (int j = 0; j < 8; j++) { O[j][2] *= corr; O[j][3] *= corr; }
        }

        // ---- O += P V ----
        #pragma unroll
        for (int kt = 0; kt < 4; kt++) {
            uint32_t ph[4], pl[4];
            {
                float p00 = S[2*kt][0],   p01 = S[2*kt][1];
                float p02 = S[2*kt][2],   p03 = S[2*kt][3];
                float p10 = S[2*kt+1][0], p11 = S[2*kt+1][1];
                float p12 = S[2*kt+1][2], p13 = S[2*kt+1][3];
                ph[0] = pack_bf16x2(p00, p01);
                ph[1] = pack_bf16x2(p02, p03);
                ph[2] = pack_bf16x2(p10, p11);
                ph[3] = pack_bf16x2(p12, p13);
                pl[0] = pack_bf16x2(p00 - bf16_rt(p00), p01 - bf16_rt(p01));
                pl[1] = pack_bf16x2(p02 - bf16_rt(p02), p03 - bf16_rt(p03));
                pl[2] = pack_bf16x2(p10 - bf16_rt(p10), p11 - bf16_rt(p11));
                pl[3] = pack_bf16x2(p12 - bf16_rt(p12), p13 - bf16_rt(p13));
            }
            #pragma unroll
            for (int g = 0; g < 4; g++) {
                uint32_t voff = ((uint32_t)(kt*16 + (lane & 15))) * 144
                              + ((uint32_t)(g*16 + (lane >> 4) * 8)) * 2;
                uint32_t vh[4], vl[4];
                LDSM_X4_T(vh, bb + 2*ATSZ + voff);
                LDSM_X4_T(vl, bb + 3*ATSZ + voff);
                MMA16816(O[2*g],   ph, vh[0], vh[1]);
                MMA16816(O[2*g],   pl, vh[0], vh[1]);
                MMA16816(O[2*g],   ph, vl[0], vl[1]);
                MMA16816(O[2*g+1], ph, vh[2], vh[3]);
                MMA16816(O[2*g+1], pl, vh[2], vh[3]);
                MMA16816(O[2*g+1], ph, vl[2], vl[3]);
            }
        }
    }

    // ---- epilogue ----
    float inv0 = 1.f / l0r, inv1 = 1.f / l1r;
    int tg0 = t0 + r0l;
    #pragma unroll
    for (int j = 0; j < 8; j++) {
        int d = h * 64 + 8*j + cb;
        {
            float v0 = O[j][0] * inv0, v1 = O[j][1] * inv0;
            __nv_bfloat16 h0 = __float2bfloat16(v0), h1 = __float2bfloat16(v1);
            size_t ad = ((size_t)tg0 * Bn + b) * En + d;
            *(__nv_bfloat162*)(g_xhi + ad) = __nv_bfloat162(h0, h1);
            *(__nv_bfloat162*)(g_xlo + ad) = __nv_bfloat162(
                __float2bfloat16(v0 - __bfloat162float(h0)),
                __float2bfloat16(v1 - __bfloat162float(h1)));
        }
        {
            float v0 = O[j][2] * inv1, v1 = O[j][3] * inv1;
            __nv_bfloat16 h0 = __float2bfloat16(v0), h1 = __float2bfloat16(v1);
            size_t ad = ((size_t)(tg0 + 8) * Bn + b) * En + d;
            *(__nv_bfloat162*)(g_xhi + ad) = __nv_bfloat162(h0, h1);
            *(__nv_bfloat162*)(g_xlo + ad) = __nv_bfloat162(
                __float2bfloat16(v0 - __bfloat162float(h0)),
                __float2bfloat16(v1 - __bfloat162float(h1)));
        }
    }
}

// ---------------- launch ----------------
extern "C" void kernel_launch(void* const* d_in, const int* in_sizes, int n_in,
                              void* d_out, int out_size) {
    const float* query  = (const float*)d_in[0];
    const float* q_w    = (const float*)d_in[1];
    const float* q_b    = (const float*)d_in[2];
    const float* k_w    = (const float*)d_in[3];
    const float* k_b    = (const float*)d_in[4];
    const float* v_w    = (const float*)d_in[5];
    const float* v_b    = (const float*)d_in[6];
    const float* out_w  = (const float*)d_in[7];
    const float* out_b  = (const float*)d_in[8];
    const float* rel_bias = (const float*)d_in[9];
    const float* grep_w = (const float*)d_in[10];
    const float* grep_b = (const float*)d_in[11];
    const float* grep_a = (const float*)d_in[12];
    float* out = (float*)d_out;

    __nv_bfloat16 *p_xhi, *p_xlo, *p_whi, *p_wlo;
    cudaGetSymbolAddress((void**)&p_xhi, g_xhi);
    cudaGetSymbolAddress((void**)&p_xlo, g_xlo);
    cudaGetSymbolAddress((void**)&p_whi, g_whi);
    cudaGetSymbolAddress((void**)&p_wlo, g_wlo);

    cudaFuncSetAttribute(gemm_qkv, cudaFuncAttributeMaxDynamicSharedMemorySize, SMEM_G);
    cudaFuncSetAttribute(gemm_out, cudaFuncAttributeMaxDynamicSharedMemorySize, SMEM_G);
    cudaFuncSetAttribute(attn_mma, cudaFuncAttributeMaxDynamicSharedMemorySize, ASM_TOTAL);

    prep_kernel<<<PREP_BLOCKS, 256>>>(query, q_w, k_w, v_w, out_w,
                                      rel_bias, grep_w, grep_b, grep_a);

    dim3 gq(24, (Tn*Bn)/128);
    gemm_qkv<<<gq, 256, SMEM_G>>>(p_xhi, p_xlo, q_b, k_b, v_b);

    dim3 ga(Tn/64, Hn, Bn);        // (16, 16, 4)
    attn_mma<<<ga, 128, ASM_TOTAL>>>();

    const int NW = En*En;
    dim3 gg(En/128, (Tn*Bn)/128);
    gemm_out<<<gg, 256, SMEM_G>>>(p_xhi, p_xlo, p_whi + 3*(size_t)NW, p_wlo + 3*(size_t)NW,
                                  out_b, out);

    (void)in_sizes; (void)n_in; (void)out_size;
}